// round 1
// baseline (speedup 1.0000x reference)
#include <cuda_runtime.h>

#define C_DIM 192
#define HEADS 6
#define HD 32
#define BATCH 128
#define SEQ 512
#define MROWS (BATCH * SEQ)   // 65536
#define LOGIT_MAX 4.6051701859880914f

// ---- scratch (device-global; no allocations allowed) ----
__device__ float g_qproj[(size_t)MROWS * C_DIM];        // 50 MB
__device__ float g_kvproj[(size_t)MROWS * 2 * C_DIM];   // 100 MB
__device__ float g_attno[(size_t)MROWS * C_DIM];        // 50 MB

// ============================================================
// Tiled fp32 GEMM: C[M,NC] = A[M,192] @ W[NC,192]^T + bias
// BM=64, BN=64, BK=16, 256 threads, 4x4 microtile per thread.
// KVB: bias is 0 for cols < 192 and v_b[col-192] for cols >= 192.
// ============================================================
template<int NC, bool KVB>
__global__ __launch_bounds__(256)
void gemm_bias_kernel(const float* __restrict__ A,
                      const float* __restrict__ W,
                      const float* __restrict__ bias,
                      float* __restrict__ C)
{
    __shared__ float As[16][64];
    __shared__ float Bs[16][64];

    const int tid  = threadIdx.x;
    const int row0 = blockIdx.y * 64;
    const int col0 = blockIdx.x * 64;
    const int ty   = tid >> 4;        // 0..15
    const int tx   = tid & 15;        // 0..15
    const int lr   = tid >> 2;        // 0..63 (load row)
    const int lk   = (tid & 3) * 4;   // 0,4,8,12 (load k offset)

    float acc[4][4] = {};

    for (int k0 = 0; k0 < C_DIM; k0 += 16) {
        float4 av = *(const float4*)&A[(size_t)(row0 + lr) * C_DIM + k0 + lk];
        float4 wv = *(const float4*)&W[(size_t)(col0 + lr) * C_DIM + k0 + lk];
        As[lk + 0][lr] = av.x; As[lk + 1][lr] = av.y;
        As[lk + 2][lr] = av.z; As[lk + 3][lr] = av.w;
        Bs[lk + 0][lr] = wv.x; Bs[lk + 1][lr] = wv.y;
        Bs[lk + 2][lr] = wv.z; Bs[lk + 3][lr] = wv.w;
        __syncthreads();

#pragma unroll
        for (int k = 0; k < 16; k++) {
            float4 ra = *(const float4*)&As[k][ty * 4];
            float4 rb = *(const float4*)&Bs[k][tx * 4];
            float a_[4] = {ra.x, ra.y, ra.z, ra.w};
            float b_[4] = {rb.x, rb.y, rb.z, rb.w};
#pragma unroll
            for (int i = 0; i < 4; i++)
#pragma unroll
                for (int j = 0; j < 4; j++)
                    acc[i][j] += a_[i] * b_[j];
        }
        __syncthreads();
    }

#pragma unroll
    for (int i = 0; i < 4; i++) {
        const int r = row0 + ty * 4 + i;
#pragma unroll
        for (int j = 0; j < 4; j++) {
            const int c = col0 + tx * 4 + j;
            float bv;
            if (KVB) bv = (c >= C_DIM) ? bias[c - C_DIM] : 0.0f;
            else     bv = bias[c];
            C[(size_t)r * NC + c] = acc[i][j] + bv;
        }
    }
}

// ============================================================
// In-place L2 normalization of q and k rows (per head, D=32).
// One warp per (row, head, {q|k}).
// ============================================================
__global__ __launch_bounds__(256)
void normalize_kernel()
{
    const int warp_id = (blockIdx.x * blockDim.x + threadIdx.x) >> 5;
    const int lane    = threadIdx.x & 31;
    const int total   = MROWS * HEADS;
    const bool is_k   = warp_id >= total;
    const int id      = is_k ? warp_id - total : warp_id;
    const int row     = id / HEADS;
    const int h       = id % HEADS;

    float* ptr = is_k ? &g_kvproj[(size_t)row * (2 * C_DIM) + h * HD]
                      : &g_qproj[(size_t)row * C_DIM + h * HD];

    float v  = ptr[lane];
    float ss = v * v;
#pragma unroll
    for (int o = 16; o; o >>= 1) ss += __shfl_xor_sync(0xffffffffu, ss, o);
    float nrm = sqrtf(ss);
    ptr[lane] = v / fmaxf(nrm, 1e-12f);
}

// ============================================================
// Attention per (b,h): S = Qn Kn^T * scale, softmax, O = P V.
// Q, K^T, V fully SMEM-resident (192 KB) + 8 KB p-staging.
// 16 warps, 32 q-rows per warp, processed 4 rows at a time.
// All 512 scores for 4 rows live in registers (16 keys/lane).
// ============================================================
__global__ __launch_bounds__(512, 1)
void attn_kernel(const float* __restrict__ ls, float* __restrict__ out)
{
    extern __shared__ float sm[];
    float*  Qs   = sm;                       // [512][32]
    float*  kT   = sm + 512 * 32;            // [32][512]
    float*  Vs   = sm + 2 * 512 * 32;        // [512][32]
    float4* sbuf = (float4*)(sm + 3 * 512 * 32); // [16 warps][32]

    const int bh   = blockIdx.x;
    const int b    = bh / HEADS;
    const int h    = bh % HEADS;
    const int tid  = threadIdx.x;
    const int w    = tid >> 5;
    const int lane = tid & 31;

    const float sc = __expf(fminf(ls[h], LOGIT_MAX));

    const float* qbase = g_qproj  + (size_t)b * SEQ * C_DIM       + h * HD;
    const float* kbase = g_kvproj + (size_t)b * SEQ * (2 * C_DIM) + h * HD;
    const float* vbase = kbase + C_DIM;

    // ---- cooperative load: Q, K(transposed), V ----
    for (int idx = tid; idx < SEQ * 8; idx += 512) {
        const int n  = idx >> 3;
        const int d0 = (idx & 7) * 4;
        float4 q4 = *(const float4*)(qbase + (size_t)n * C_DIM + d0);
        *(float4*)(Qs + n * 32 + d0) = q4;
        float4 k4 = *(const float4*)(kbase + (size_t)n * (2 * C_DIM) + d0);
        kT[(d0 + 0) * SEQ + n] = k4.x;
        kT[(d0 + 1) * SEQ + n] = k4.y;
        kT[(d0 + 2) * SEQ + n] = k4.z;
        kT[(d0 + 3) * SEQ + n] = k4.w;
        float4 v4 = *(const float4*)(vbase + (size_t)n * (2 * C_DIM) + d0);
        *(float4*)(Vs + n * 32 + d0) = v4;
    }
    __syncthreads();

    float4* sbw = sbuf + w * 32;

    for (int g = 0; g < 8; g++) {
        const int r0 = w * 32 + g * 4;

        // ---- phase 1: scores. lane owns keys {lane + 32*i} ----
        float s0[16] = {}, s1[16] = {}, s2[16] = {}, s3[16] = {};
#pragma unroll 4
        for (int d = 0; d < 32; d++) {
            const float q0 = Qs[(r0 + 0) * 32 + d];
            const float q1 = Qs[(r0 + 1) * 32 + d];
            const float q2 = Qs[(r0 + 2) * 32 + d];
            const float q3 = Qs[(r0 + 3) * 32 + d];
            const float* kd = kT + d * SEQ + lane;
#pragma unroll
            for (int i = 0; i < 16; i++) {
                const float kv = kd[i * 32];
                s0[i] += q0 * kv; s1[i] += q1 * kv;
                s2[i] += q2 * kv; s3[i] += q3 * kv;
            }
        }

        // ---- softmax (exact, all keys in regs) ----
        float m0 = -1e30f, m1 = -1e30f, m2 = -1e30f, m3 = -1e30f;
#pragma unroll
        for (int i = 0; i < 16; i++) {
            m0 = fmaxf(m0, s0[i]); m1 = fmaxf(m1, s1[i]);
            m2 = fmaxf(m2, s2[i]); m3 = fmaxf(m3, s3[i]);
        }
#pragma unroll
        for (int o = 16; o; o >>= 1) {
            m0 = fmaxf(m0, __shfl_xor_sync(0xffffffffu, m0, o));
            m1 = fmaxf(m1, __shfl_xor_sync(0xffffffffu, m1, o));
            m2 = fmaxf(m2, __shfl_xor_sync(0xffffffffu, m2, o));
            m3 = fmaxf(m3, __shfl_xor_sync(0xffffffffu, m3, o));
        }
        float l0 = 0, l1 = 0, l2 = 0, l3 = 0;
#pragma unroll
        for (int i = 0; i < 16; i++) {
            s0[i] = __expf((s0[i] - m0) * sc); l0 += s0[i];
            s1[i] = __expf((s1[i] - m1) * sc); l1 += s1[i];
            s2[i] = __expf((s2[i] - m2) * sc); l2 += s2[i];
            s3[i] = __expf((s3[i] - m3) * sc); l3 += s3[i];
        }
#pragma unroll
        for (int o = 16; o; o >>= 1) {
            l0 += __shfl_xor_sync(0xffffffffu, l0, o);
            l1 += __shfl_xor_sync(0xffffffffu, l1, o);
            l2 += __shfl_xor_sync(0xffffffffu, l2, o);
            l3 += __shfl_xor_sync(0xffffffffu, l3, o);
        }

        // ---- phase 2: O = P V. lane owns output dim d = lane ----
        float o0 = 0, o1 = 0, o2 = 0, o3 = 0;
#pragma unroll
        for (int i = 0; i < 16; i++) {
            sbw[lane] = make_float4(s0[i], s1[i], s2[i], s3[i]);
            __syncwarp();
            const float* vp = Vs + i * 32 * 32 + lane;
#pragma unroll
            for (int jj = 0; jj < 32; jj++) {
                const float4 p4 = sbw[jj];   // broadcast
                const float  vv = vp[jj * 32];
                o0 += p4.x * vv; o1 += p4.y * vv;
                o2 += p4.z * vv; o3 += p4.w * vv;
            }
            __syncwarp();
        }

        float* ob = out + (size_t)(b * SEQ + r0) * C_DIM + h * HD + lane;
        ob[0 * C_DIM] = o0 / l0;
        ob[1 * C_DIM] = o1 / l1;
        ob[2 * C_DIM] = o2 / l2;
        ob[3 * C_DIM] = o3 / l3;
    }
}

// ============================================================
// Launch
// ============================================================
extern "C" void kernel_launch(void* const* d_in, const int* in_sizes, int n_in,
                              void* d_out, int out_size)
{
    (void)in_sizes; (void)n_in; (void)out_size;
    const float* x1     = (const float*)d_in[0];
    const float* x2     = (const float*)d_in[1];
    const float* q_w    = (const float*)d_in[2];
    const float* q_b    = (const float*)d_in[3];
    const float* kv_w   = (const float*)d_in[4];
    const float* v_b    = (const float*)d_in[5];
    const float* ls     = (const float*)d_in[6];
    const float* proj_w = (const float*)d_in[7];
    const float* proj_b = (const float*)d_in[8];
    float* out = (float*)d_out;

    float *qproj, *kvproj, *attno;
    cudaGetSymbolAddress((void**)&qproj,  g_qproj);
    cudaGetSymbolAddress((void**)&kvproj, g_kvproj);
    cudaGetSymbolAddress((void**)&attno,  g_attno);

    const dim3 blk(256);

    // 1) q projection
    gemm_bias_kernel<C_DIM, false><<<dim3(C_DIM / 64, MROWS / 64), blk>>>(x1, q_w, q_b, qproj);
    // 2) kv projection (bias = [0; v_b])
    gemm_bias_kernel<2 * C_DIM, true><<<dim3(2 * C_DIM / 64, MROWS / 64), blk>>>(x2, kv_w, v_b, kvproj);
    // 3) normalize q and k in place
    normalize_kernel<<<(2 * MROWS * HEADS) / 8, 256>>>();
    // 4) attention
    const int smem_bytes = 3 * 512 * 32 * 4 + 16 * 32 * 16;  // 204800
    cudaFuncSetAttribute(attn_kernel, cudaFuncAttributeMaxDynamicSharedMemorySize, smem_bytes);
    attn_kernel<<<BATCH * HEADS, 512, smem_bytes>>>(ls, attno);
    // 5) output projection
    gemm_bias_kernel<C_DIM, false><<<dim3(C_DIM / 64, MROWS / 64), blk>>>(attno, proj_w, proj_b, out);
}

// round 2
// speedup vs baseline: 2.7599x; 2.7599x over previous
#include <cuda_runtime.h>
#include <cuda_fp16.h>

#define C_DIM 192
#define HEADS 6
#define HD 32
#define BATCH 128
#define SEQ 512
#define MROWS (BATCH * SEQ)        // 65536
#define BH (BATCH * HEADS)         // 768
#define LOGIT_MAX 4.6051701859880914f

// ---------------- device-global scratch ----------------
__device__ float  g_qf[(size_t)BH * SEQ * HD];    // fp32 q, head-major
__device__ float  g_kf[(size_t)BH * SEQ * HD];    // fp32 k, head-major
__device__ __half g_qh[(size_t)BH * SEQ * HD];    // split q hi (normalized*scale)
__device__ __half g_ql[(size_t)BH * SEQ * HD];    // split q lo
__device__ __half g_kh[(size_t)BH * SEQ * HD];    // split k hi (normalized)
__device__ __half g_kl[(size_t)BH * SEQ * HD];    // split k lo
__device__ __half g_vt[(size_t)BH * HD * SEQ];    // v transposed per (b,h): [d][n]
__device__ __half g_attno[(size_t)MROWS * C_DIM]; // attention output fp16

// ---------------- helpers ----------------
__device__ __forceinline__ unsigned smem_u32(const void* p) {
    return (unsigned)__cvta_generic_to_shared(p);
}
__device__ __forceinline__ void ldsm4(unsigned& r0, unsigned& r1, unsigned& r2, unsigned& r3, unsigned a) {
    asm volatile("ldmatrix.sync.aligned.m8n8.x4.shared.b16 {%0,%1,%2,%3},[%4];\n"
                 : "=r"(r0), "=r"(r1), "=r"(r2), "=r"(r3) : "r"(a));
}
__device__ __forceinline__ void mma16816(float* c, unsigned a0, unsigned a1, unsigned a2, unsigned a3,
                                         unsigned b0, unsigned b1) {
    asm volatile("mma.sync.aligned.m16n8k16.row.col.f32.f16.f16.f32 "
                 "{%0,%1,%2,%3},{%4,%5,%6,%7},{%8,%9},{%0,%1,%2,%3};\n"
                 : "+f"(c[0]), "+f"(c[1]), "+f"(c[2]), "+f"(c[3])
                 : "r"(a0), "r"(a1), "r"(a2), "r"(a3), "r"(b0), "r"(b1));
}
__device__ __forceinline__ void split2(float x, float y, __half2& hi, __half2& lo) {
    __half hx = __float2half_rn(x), hy = __float2half_rn(y);
    hi = __halves2half2(hx, hy);
    lo = __floats2half2_rn(x - __half2float(hx), y - __half2float(hy));
}
__device__ __forceinline__ unsigned pack_h2(float a, float b) {
    __half2 t = __floats2half2_rn(a, b);
    return *(unsigned*)&t;
}

// ============================================================
// Split-fp16 tensor-core GEMM: C[M,NC] = A[M,192] @ W[NC,192]^T
// BM=128, BN=64, BK=32, 256 threads, 8 warps (4m x 2n), warp tile 32x32.
// MODE 0: A=f32 (split), out fp32 -> g_qf head-major (+q_b)        [3 terms]
// MODE 1: A=f32 (split), out k->g_kf, v->g_vt half (+v_b)          [3 terms]
// MODE 2: A=half single, out fp32 d_out (+bias), W split           [2 terms]
// ============================================================
template<int NC, int MODE>
__global__ __launch_bounds__(256)
void gemm_kernel(const void* __restrict__ Ain, const float* __restrict__ W,
                 const float* __restrict__ bias, float* __restrict__ outf)
{
    constexpr bool A_HALF = (MODE == 2);
    __shared__ __half Ah[128][40];
    __shared__ __half Al[A_HALF ? 8 : 128][40];
    __shared__ __half Bh[64][40];
    __shared__ __half Bl[64][40];

    const int tid = threadIdx.x, w = tid >> 5, lane = tid & 31;
    const int wm = w >> 1, wn = w & 1;
    const int row0 = blockIdx.y * 128, col0 = blockIdx.x * 64;

    float acc[2][4][4] = {};

    for (int k0 = 0; k0 < C_DIM; k0 += 32) {
        // ---- load A tile ----
        if (!A_HALF) {
            const float* A = (const float*)Ain;
#pragma unroll
            for (int p = 0; p < 4; p++) {
                int idx = p * 256 + tid;
                int r = idx >> 3, c = (idx & 7) * 4;
                float4 v = *(const float4*)&A[(size_t)(row0 + r) * C_DIM + k0 + c];
                __half2 h0, l0, h1, l1;
                split2(v.x, v.y, h0, l0);
                split2(v.z, v.w, h1, l1);
                *(__half2*)&Ah[r][c] = h0; *(__half2*)&Ah[r][c + 2] = h1;
                *(__half2*)&Al[r][c] = l0; *(__half2*)&Al[r][c + 2] = l1;
            }
        } else {
            const __half* A = (const __half*)Ain;
#pragma unroll
            for (int p = 0; p < 2; p++) {
                int idx = p * 256 + tid;
                int r = idx >> 2, c8 = (idx & 3) * 8;
                *(uint4*)&Ah[r][c8] = *(const uint4*)&A[(size_t)(row0 + r) * C_DIM + k0 + c8];
            }
        }
        // ---- load W tile (always split) ----
#pragma unroll
        for (int p = 0; p < 2; p++) {
            int idx = p * 256 + tid;
            int r = idx >> 3, c = (idx & 7) * 4;
            float4 v = *(const float4*)&W[(size_t)(col0 + r) * C_DIM + k0 + c];
            __half2 h0, l0, h1, l1;
            split2(v.x, v.y, h0, l0);
            split2(v.z, v.w, h1, l1);
            *(__half2*)&Bh[r][c] = h0; *(__half2*)&Bh[r][c + 2] = h1;
            *(__half2*)&Bl[r][c] = l0; *(__half2*)&Bl[r][c + 2] = l1;
        }
        __syncthreads();

        // ---- compute ----
#pragma unroll
        for (int kf = 0; kf < 2; kf++) {
            unsigned ah[2][4], al[2][4];
#pragma unroll
            for (int mf = 0; mf < 2; mf++) {
                unsigned a = smem_u32(&Ah[wm * 32 + mf * 16 + (lane & 15)][kf * 16 + (lane >> 4) * 8]);
                ldsm4(ah[mf][0], ah[mf][1], ah[mf][2], ah[mf][3], a);
                if (!A_HALF) {
                    a = smem_u32(&Al[wm * 32 + mf * 16 + (lane & 15)][kf * 16 + (lane >> 4) * 8]);
                    ldsm4(al[mf][0], al[mf][1], al[mf][2], al[mf][3], a);
                }
            }
            unsigned bh_[4][2], bl_[4][2];
#pragma unroll
            for (int nt2 = 0; nt2 < 2; nt2++) {
                int rowb = wn * 32 + nt2 * 16 + ((lane >> 4) << 3) + (lane & 7);
                int colb = kf * 16 + ((lane >> 3) & 1) * 8;
                unsigned r0, r1, r2, r3;
                ldsm4(r0, r1, r2, r3, smem_u32(&Bh[rowb][colb]));
                bh_[nt2 * 2][0] = r0; bh_[nt2 * 2][1] = r1;
                bh_[nt2 * 2 + 1][0] = r2; bh_[nt2 * 2 + 1][1] = r3;
                ldsm4(r0, r1, r2, r3, smem_u32(&Bl[rowb][colb]));
                bl_[nt2 * 2][0] = r0; bl_[nt2 * 2][1] = r1;
                bl_[nt2 * 2 + 1][0] = r2; bl_[nt2 * 2 + 1][1] = r3;
            }
#pragma unroll
            for (int mf = 0; mf < 2; mf++)
#pragma unroll
                for (int nt = 0; nt < 4; nt++) {
                    mma16816(acc[mf][nt], ah[mf][0], ah[mf][1], ah[mf][2], ah[mf][3], bh_[nt][0], bh_[nt][1]);
                    mma16816(acc[mf][nt], ah[mf][0], ah[mf][1], ah[mf][2], ah[mf][3], bl_[nt][0], bl_[nt][1]);
                    if (!A_HALF)
                        mma16816(acc[mf][nt], al[mf][0], al[mf][1], al[mf][2], al[mf][3], bh_[nt][0], bh_[nt][1]);
                }
        }
        __syncthreads();
    }

    // ---- epilogue ----
#pragma unroll
    for (int mf = 0; mf < 2; mf++) {
        const int rlo = row0 + wm * 32 + mf * 16 + (lane >> 2);
#pragma unroll
        for (int nt = 0; nt < 4; nt++) {
            const int cc = col0 + wn * 32 + nt * 8 + (lane & 3) * 2;
#pragma unroll
            for (int half_ = 0; half_ < 2; half_++) {
                const int r = rlo + half_ * 8;
                const float v0 = acc[mf][nt][half_ * 2 + 0];
                const float v1 = acc[mf][nt][half_ * 2 + 1];
                if (MODE == 2) {
                    float2 o = make_float2(v0 + bias[cc], v1 + bias[cc + 1]);
                    *(float2*)&outf[(size_t)r * C_DIM + cc] = o;
                } else if (MODE == 0) {
                    const int b = r >> 9, n = r & 511, h = cc >> 5, d = cc & 31;
                    float2 o = make_float2(v0 + bias[cc], v1 + bias[cc + 1]);
                    *(float2*)&g_qf[(((size_t)(b * HEADS + h) << 9) | n) * HD + d] = o;
                } else { // MODE 1
                    const int b = r >> 9, n = r & 511;
                    if (cc < C_DIM) {
                        const int h = cc >> 5, d = cc & 31;
                        float2 o = make_float2(v0, v1);
                        *(float2*)&g_kf[(((size_t)(b * HEADS + h) << 9) | n) * HD + d] = o;
                    } else {
                        const int cv = cc - C_DIM, h = cv >> 5, d = cv & 31;
                        g_vt[((size_t)(b * HEADS + h) * HD + d) * SEQ + n]     = __float2half_rn(v0 + bias[cv]);
                        g_vt[((size_t)(b * HEADS + h) * HD + d + 1) * SEQ + n] = __float2half_rn(v1 + bias[cv + 1]);
                    }
                }
            }
        }
    }
}

// ============================================================
// Normalize q (x per-head scale) and k; emit split fp16.
// One warp per 8 rows; 4 lanes per row (8 elems each).
// ============================================================
__global__ __launch_bounds__(256)
void norm_kernel(const float* __restrict__ ls)
{
    const int g = blockIdx.x * 256 + threadIdx.x;
    const int wid = g >> 5, lane = g & 31;
    const int row = wid * 8 + (lane >> 2);
    const int q4 = lane & 3;
    const bool is_q = row < BH * SEQ;
    const int rr = is_q ? row : row - BH * SEQ;

    const float* src = (is_q ? g_qf : g_kf) + (size_t)rr * HD + q4 * 8;
    float4 v0 = *(const float4*)&src[0];
    float4 v1 = *(const float4*)&src[4];
    float ss = v0.x * v0.x + v0.y * v0.y + v0.z * v0.z + v0.w * v0.w
             + v1.x * v1.x + v1.y * v1.y + v1.z * v1.z + v1.w * v1.w;
    ss += __shfl_xor_sync(0xffffffffu, ss, 1);
    ss += __shfl_xor_sync(0xffffffffu, ss, 2);
    float inv = 1.0f / fmaxf(sqrtf(ss), 1e-12f);
    if (is_q) {
        const int h = (rr >> 9) % HEADS;
        inv *= __expf(fminf(ls[h], LOGIT_MAX));
    }

    __half2 hi[4], lo[4];
    split2(v0.x * inv, v0.y * inv, hi[0], lo[0]);
    split2(v0.z * inv, v0.w * inv, hi[1], lo[1]);
    split2(v1.x * inv, v1.y * inv, hi[2], lo[2]);
    split2(v1.z * inv, v1.w * inv, hi[3], lo[3]);

    __half* dh = (is_q ? g_qh : g_kh) + (size_t)rr * HD + q4 * 8;
    __half* dl = (is_q ? g_ql : g_kl) + (size_t)rr * HD + q4 * 8;
    *(uint4*)dh = *(uint4*)hi;
    *(uint4*)dl = *(uint4*)lo;
}

// ============================================================
// FlashAttention-2 style per (b,h) block. 256 thr, 8 warps.
// K(hi,lo) + V^T in smem (112.5 KB); Q frags from gmem.
// QK^T 3-term split mma, online softmax, PV single mma.
// ============================================================
__global__ __launch_bounds__(256, 2)
void attn_kernel()
{
    extern __shared__ __half sm[];
    __half* Khs = sm;                    // [512][40]
    __half* Kls = sm + 512 * 40;         // [512][40]
    __half* Vts = sm + 2 * 512 * 40;     // [32][520]

    const int bh = blockIdx.x;
    const int b = bh / HEADS, h = bh % HEADS;
    const int tid = threadIdx.x, w = tid >> 5, lane = tid & 31;

    const __half* kh = g_kh + (size_t)bh * SEQ * HD;
    const __half* kl = g_kl + (size_t)bh * SEQ * HD;
    const __half* vt = g_vt + (size_t)bh * HD * SEQ;

#pragma unroll
    for (int p = 0; p < 8; p++) {
        int idx = p * 256 + tid;
        int r = idx >> 2, c8 = (idx & 3) * 8;
        *(uint4*)&Khs[r * 40 + c8] = *(const uint4*)&kh[r * HD + c8];
        *(uint4*)&Kls[r * 40 + c8] = *(const uint4*)&kl[r * HD + c8];
    }
#pragma unroll
    for (int p = 0; p < 8; p++) {
        int idx = p * 256 + tid;
        int d = idx >> 6, c8 = (idx & 63) * 8;
        *(uint4*)&Vts[d * 520 + c8] = *(const uint4*)&vt[d * SEQ + c8];
    }
    __syncthreads();

    const __half* qh = g_qh + (size_t)bh * SEQ * HD;
    const __half* ql = g_ql + (size_t)bh * SEQ * HD;

    for (int mf = 0; mf < 4; mf++) {
        const int m0 = w * 64 + mf * 16;
        const int rlo = m0 + (lane >> 2);

        unsigned qhf[2][4], qlf[2][4];
#pragma unroll
        for (int kf = 0; kf < 2; kf++) {
            const int kb = kf * 16 + (lane & 3) * 2;
            qhf[kf][0] = *(const unsigned*)&qh[(size_t)rlo * HD + kb];
            qhf[kf][1] = *(const unsigned*)&qh[(size_t)(rlo + 8) * HD + kb];
            qhf[kf][2] = *(const unsigned*)&qh[(size_t)rlo * HD + kb + 8];
            qhf[kf][3] = *(const unsigned*)&qh[(size_t)(rlo + 8) * HD + kb + 8];
            qlf[kf][0] = *(const unsigned*)&ql[(size_t)rlo * HD + kb];
            qlf[kf][1] = *(const unsigned*)&ql[(size_t)(rlo + 8) * HD + kb];
            qlf[kf][2] = *(const unsigned*)&ql[(size_t)rlo * HD + kb + 8];
            qlf[kf][3] = *(const unsigned*)&ql[(size_t)(rlo + 8) * HD + kb + 8];
        }

        float O[4][4] = {};
        float m_lo = -1e30f, m_hi = -1e30f, l_lo = 0.f, l_hi = 0.f;

        for (int kc = 0; kc < 8; kc++) {
            float S[8][4] = {};
#pragma unroll
            for (int nt2 = 0; nt2 < 4; nt2++) {
                const int rowb = kc * 64 + nt2 * 16 + ((lane >> 4) << 3) + (lane & 7);
                const int colb = ((lane >> 3) & 1) * 8;
#pragma unroll
                for (int kf = 0; kf < 2; kf++) {
                    unsigned kh0, kh1, kh2, kh3, kl0, kl1, kl2, kl3;
                    ldsm4(kh0, kh1, kh2, kh3, smem_u32(&Khs[rowb * 40 + kf * 16 + colb]));
                    ldsm4(kl0, kl1, kl2, kl3, smem_u32(&Kls[rowb * 40 + kf * 16 + colb]));
                    float* SA = S[nt2 * 2];
                    float* SB = S[nt2 * 2 + 1];
                    mma16816(SA, qhf[kf][0], qhf[kf][1], qhf[kf][2], qhf[kf][3], kh0, kh1);
                    mma16816(SB, qhf[kf][0], qhf[kf][1], qhf[kf][2], qhf[kf][3], kh2, kh3);
                    mma16816(SA, qhf[kf][0], qhf[kf][1], qhf[kf][2], qhf[kf][3], kl0, kl1);
                    mma16816(SB, qhf[kf][0], qhf[kf][1], qhf[kf][2], qhf[kf][3], kl2, kl3);
                    mma16816(SA, qlf[kf][0], qlf[kf][1], qlf[kf][2], qlf[kf][3], kh0, kh1);
                    mma16816(SB, qlf[kf][0], qlf[kf][1], qlf[kf][2], qlf[kf][3], kh2, kh3);
                }
            }

            // ---- online softmax ----
            float mx_lo = -1e30f, mx_hi = -1e30f;
#pragma unroll
            for (int nt = 0; nt < 8; nt++) {
                mx_lo = fmaxf(mx_lo, fmaxf(S[nt][0], S[nt][1]));
                mx_hi = fmaxf(mx_hi, fmaxf(S[nt][2], S[nt][3]));
            }
            mx_lo = fmaxf(mx_lo, __shfl_xor_sync(0xffffffffu, mx_lo, 1));
            mx_lo = fmaxf(mx_lo, __shfl_xor_sync(0xffffffffu, mx_lo, 2));
            mx_hi = fmaxf(mx_hi, __shfl_xor_sync(0xffffffffu, mx_hi, 1));
            mx_hi = fmaxf(mx_hi, __shfl_xor_sync(0xffffffffu, mx_hi, 2));

            const float mn_lo = fmaxf(m_lo, mx_lo), mn_hi = fmaxf(m_hi, mx_hi);
            const float rs_lo = __expf(m_lo - mn_lo), rs_hi = __expf(m_hi - mn_hi);
            m_lo = mn_lo; m_hi = mn_hi;

            float s_lo = 0.f, s_hi = 0.f;
#pragma unroll
            for (int nt = 0; nt < 8; nt++) {
                S[nt][0] = __expf(S[nt][0] - mn_lo);
                S[nt][1] = __expf(S[nt][1] - mn_lo);
                S[nt][2] = __expf(S[nt][2] - mn_hi);
                S[nt][3] = __expf(S[nt][3] - mn_hi);
                s_lo += S[nt][0] + S[nt][1];
                s_hi += S[nt][2] + S[nt][3];
            }
            s_lo += __shfl_xor_sync(0xffffffffu, s_lo, 1);
            s_lo += __shfl_xor_sync(0xffffffffu, s_lo, 2);
            s_hi += __shfl_xor_sync(0xffffffffu, s_hi, 1);
            s_hi += __shfl_xor_sync(0xffffffffu, s_hi, 2);
            l_lo = l_lo * rs_lo + s_lo;
            l_hi = l_hi * rs_hi + s_hi;
#pragma unroll
            for (int dt = 0; dt < 4; dt++) {
                O[dt][0] *= rs_lo; O[dt][1] *= rs_lo;
                O[dt][2] *= rs_hi; O[dt][3] *= rs_hi;
            }

            // ---- PV ----
#pragma unroll
            for (int ks = 0; ks < 4; ks++) {
                const unsigned p0 = pack_h2(S[2 * ks][0], S[2 * ks][1]);
                const unsigned p1 = pack_h2(S[2 * ks][2], S[2 * ks][3]);
                const unsigned p2 = pack_h2(S[2 * ks + 1][0], S[2 * ks + 1][1]);
                const unsigned p3 = pack_h2(S[2 * ks + 1][2], S[2 * ks + 1][3]);
#pragma unroll
                for (int dt2 = 0; dt2 < 2; dt2++) {
                    const int rowd = dt2 * 16 + ((lane >> 4) << 3) + (lane & 7);
                    const int colk = kc * 64 + ks * 16 + ((lane >> 3) & 1) * 8;
                    unsigned v0, v1, v2, v3;
                    ldsm4(v0, v1, v2, v3, smem_u32(&Vts[rowd * 520 + colk]));
                    mma16816(O[dt2 * 2],     p0, p1, p2, p3, v0, v1);
                    mma16816(O[dt2 * 2 + 1], p0, p1, p2, p3, v2, v3);
                }
            }
        }

        // ---- write ----
        const float il_lo = 1.0f / l_lo, il_hi = 1.0f / l_hi;
#pragma unroll
        for (int dt = 0; dt < 4; dt++) {
            __half2 o_lo = __floats2half2_rn(O[dt][0] * il_lo, O[dt][1] * il_lo);
            __half2 o_hi = __floats2half2_rn(O[dt][2] * il_hi, O[dt][3] * il_hi);
            const size_t base = ((size_t)b * SEQ + rlo) * C_DIM + h * HD + dt * 8 + (lane & 3) * 2;
            *(__half2*)&g_attno[base] = o_lo;
            *(__half2*)&g_attno[base + (size_t)8 * C_DIM] = o_hi;
        }
    }
}

// ============================================================
// Launch
// ============================================================
extern "C" void kernel_launch(void* const* d_in, const int* in_sizes, int n_in,
                              void* d_out, int out_size)
{
    (void)in_sizes; (void)n_in; (void)out_size;
    const float* x1     = (const float*)d_in[0];
    const float* x2     = (const float*)d_in[1];
    const float* q_w    = (const float*)d_in[2];
    const float* q_b    = (const float*)d_in[3];
    const float* kv_w   = (const float*)d_in[4];
    const float* v_b    = (const float*)d_in[5];
    const float* ls     = (const float*)d_in[6];
    const float* proj_w = (const float*)d_in[7];
    const float* proj_b = (const float*)d_in[8];
    float* out = (float*)d_out;

    __half* attno;
    cudaGetSymbolAddress((void**)&attno, g_attno);

    // 1) q projection (split fp16, fp32 out head-major)
    gemm_kernel<C_DIM, 0><<<dim3(C_DIM / 64, MROWS / 128), 256>>>(x1, q_w, q_b, nullptr);
    // 2) kv projection (split fp16; k fp32 head-major, v fp16 transposed)
    gemm_kernel<2 * C_DIM, 1><<<dim3(2 * C_DIM / 64, MROWS / 128), 256>>>(x2, kv_w, v_b, nullptr);
    // 3) normalize + scale-fold + split to fp16
    norm_kernel<<<(2 * BH * SEQ * 4) / 256, 256>>>(ls);
    // 4) attention
    const int smem_bytes = (2 * 512 * 40 + 32 * 520) * (int)sizeof(__half); // 115200
    cudaFuncSetAttribute(attn_kernel, cudaFuncAttributeMaxDynamicSharedMemorySize, smem_bytes);
    attn_kernel<<<BH, 256, smem_bytes>>>();
    // 5) output projection (A fp16 single, W split)
    gemm_kernel<C_DIM, 2><<<dim3(C_DIM / 64, MROWS / 128), 256>>>(attno, proj_w, proj_b, out);
}

// round 3
// speedup vs baseline: 3.8556x; 1.3970x over previous
#include <cuda_runtime.h>
#include <cuda_fp16.h>

#define C_DIM 192
#define HEADS 6
#define HD 32
#define BATCH 128
#define SEQ 512
#define MROWS (BATCH * SEQ)        // 65536
#define BH (BATCH * HEADS)         // 768
#define LOGIT_MAX 4.6051701859880914f

// ---------------- device-global scratch ----------------
__device__ float  g_qf[(size_t)BH * SEQ * HD];
__device__ float  g_kf[(size_t)BH * SEQ * HD];
__device__ __half g_qh[(size_t)BH * SEQ * HD];
__device__ __half g_ql[(size_t)BH * SEQ * HD];
__device__ __half g_kh[(size_t)BH * SEQ * HD];
__device__ __half g_kl[(size_t)BH * SEQ * HD];
__device__ __half g_vt[(size_t)BH * HD * SEQ];
__device__ __half g_attno[(size_t)MROWS * C_DIM];
// pre-split inputs / weights
__device__ __half g_x1h[(size_t)MROWS * C_DIM];
__device__ __half g_x1l[(size_t)MROWS * C_DIM];
__device__ __half g_x2h[(size_t)MROWS * C_DIM];
__device__ __half g_x2l[(size_t)MROWS * C_DIM];
__device__ __half g_wqh[C_DIM * C_DIM];
__device__ __half g_wql[C_DIM * C_DIM];
__device__ __half g_wkvh[2 * C_DIM * C_DIM];
__device__ __half g_wkvl[2 * C_DIM * C_DIM];
__device__ __half g_wph[C_DIM * C_DIM];
__device__ __half g_wpl[C_DIM * C_DIM];

// ---------------- helpers ----------------
__device__ __forceinline__ unsigned smem_u32(const void* p) {
    return (unsigned)__cvta_generic_to_shared(p);
}
__device__ __forceinline__ void ldsm4(unsigned& r0, unsigned& r1, unsigned& r2, unsigned& r3, unsigned a) {
    asm volatile("ldmatrix.sync.aligned.m8n8.x4.shared.b16 {%0,%1,%2,%3},[%4];\n"
                 : "=r"(r0), "=r"(r1), "=r"(r2), "=r"(r3) : "r"(a));
}
__device__ __forceinline__ void mma16816(float* c, unsigned a0, unsigned a1, unsigned a2, unsigned a3,
                                         unsigned b0, unsigned b1) {
    asm volatile("mma.sync.aligned.m16n8k16.row.col.f32.f16.f16.f32 "
                 "{%0,%1,%2,%3},{%4,%5,%6,%7},{%8,%9},{%0,%1,%2,%3};\n"
                 : "+f"(c[0]), "+f"(c[1]), "+f"(c[2]), "+f"(c[3])
                 : "r"(a0), "r"(a1), "r"(a2), "r"(a3), "r"(b0), "r"(b1));
}
__device__ __forceinline__ void split2(float x, float y, __half2& hi, __half2& lo) {
    __half hx = __float2half_rn(x), hy = __float2half_rn(y);
    hi = __halves2half2(hx, hy);
    lo = __floats2half2_rn(x - __half2float(hx), y - __half2float(hy));
}
__device__ __forceinline__ unsigned pack_h2(float a, float b) {
    __half2 t = __floats2half2_rn(a, b);
    return *(unsigned*)&t;
}
__device__ __forceinline__ void cpa16(void* s, const void* g) {
    asm volatile("cp.async.ca.shared.global [%0], [%1], 16;\n" :: "r"(smem_u32(s)), "l"(g));
}
__device__ __forceinline__ void cpa_commit() { asm volatile("cp.async.commit_group;\n"); }
__device__ __forceinline__ void cpa_wait1()  { asm volatile("cp.async.wait_group 1;\n"); }
__device__ __forceinline__ void cpa_wait0()  { asm volatile("cp.async.wait_group 0;\n"); }

// ============================================================
// Pre-split fp32 -> (hi, lo) fp16. 8 elems per thread.
// ============================================================
__global__ __launch_bounds__(256)
void split_kernel(const float* __restrict__ src, __half* __restrict__ hi,
                  __half* __restrict__ lo, int n8)
{
    const int i = blockIdx.x * 256 + threadIdx.x;
    if (i >= n8) return;
    const float4 a = *(const float4*)&src[(size_t)i * 8];
    const float4 b = *(const float4*)&src[(size_t)i * 8 + 4];
    __half2 h[4], l[4];
    split2(a.x, a.y, h[0], l[0]);
    split2(a.z, a.w, h[1], l[1]);
    split2(b.x, b.y, h[2], l[2]);
    split2(b.z, b.w, h[3], l[3]);
    *(uint4*)&hi[(size_t)i * 8] = *(uint4*)h;
    *(uint4*)&lo[(size_t)i * 8] = *(uint4*)l;
}

// ============================================================
// Tensor-core GEMM on pre-split operands, cp.async double buffer.
// BM=128, BN=64, BK=32, 256 thr, 8 warps (4m x 2n).
// MODE 0: 3-term -> g_qf fp32 head-major (+q_b)
// MODE 1: 3-term -> k: g_kf fp32 head-major; v: g_vt half T (+v_b)
// MODE 2: A single half (attno), W split, 2-term -> d_out (+bias)
// ============================================================
template<int NC, int MODE>
__global__ __launch_bounds__(256)
void gemm_kernel(const __half* __restrict__ Ah_g, const __half* __restrict__ Al_g,
                 const __half* __restrict__ Wh_g, const __half* __restrict__ Wl_g,
                 const float* __restrict__ bias, float* __restrict__ outf)
{
    constexpr bool A_HALF = (MODE == 2);
    __shared__ __half Ah[2][128][40];
    __shared__ __half Al[2][A_HALF ? 8 : 128][40];
    __shared__ __half Bh[2][64][40];
    __shared__ __half Bl[2][64][40];

    const int tid = threadIdx.x, w = tid >> 5, lane = tid & 31;
    const int wm = w >> 1, wn = w & 1;
    const int row0 = blockIdx.y * 128, col0 = blockIdx.x * 64;

    auto load_stage = [&](int s, int buf) {
        const int k0 = s * 32;
#pragma unroll
        for (int j = 0; j < 2; j++) {
            const int idx = j * 256 + tid;
            const int r = idx >> 2, c8 = (idx & 3) * 8;
            cpa16(&Ah[buf][r][c8], &Ah_g[(size_t)(row0 + r) * C_DIM + k0 + c8]);
            if (!A_HALF)
                cpa16(&Al[buf][r][c8], &Al_g[(size_t)(row0 + r) * C_DIM + k0 + c8]);
        }
        {
            const int r = tid >> 2, c8 = (tid & 3) * 8;
            cpa16(&Bh[buf][r][c8], &Wh_g[(size_t)(col0 + r) * C_DIM + k0 + c8]);
            cpa16(&Bl[buf][r][c8], &Wl_g[(size_t)(col0 + r) * C_DIM + k0 + c8]);
        }
    };

    float acc[2][4][4] = {};

    load_stage(0, 0);
    cpa_commit();

    for (int s = 0; s < 6; s++) {
        const int buf = s & 1;
        if (s < 5) { load_stage(s + 1, buf ^ 1); cpa_commit(); cpa_wait1(); }
        else       { cpa_wait0(); }
        __syncthreads();

#pragma unroll
        for (int kf = 0; kf < 2; kf++) {
            unsigned ah[2][4], al[2][4];
#pragma unroll
            for (int mf = 0; mf < 2; mf++) {
                unsigned a = smem_u32(&Ah[buf][wm * 32 + mf * 16 + (lane & 15)][kf * 16 + (lane >> 4) * 8]);
                ldsm4(ah[mf][0], ah[mf][1], ah[mf][2], ah[mf][3], a);
                if (!A_HALF) {
                    a = smem_u32(&Al[buf][wm * 32 + mf * 16 + (lane & 15)][kf * 16 + (lane >> 4) * 8]);
                    ldsm4(al[mf][0], al[mf][1], al[mf][2], al[mf][3], a);
                }
            }
            unsigned bh_[4][2], bl_[4][2];
#pragma unroll
            for (int nt2 = 0; nt2 < 2; nt2++) {
                const int rowb = wn * 32 + nt2 * 16 + ((lane >> 4) << 3) + (lane & 7);
                const int colb = kf * 16 + ((lane >> 3) & 1) * 8;
                unsigned r0, r1, r2, r3;
                ldsm4(r0, r1, r2, r3, smem_u32(&Bh[buf][rowb][colb]));
                bh_[nt2 * 2][0] = r0; bh_[nt2 * 2][1] = r1;
                bh_[nt2 * 2 + 1][0] = r2; bh_[nt2 * 2 + 1][1] = r3;
                ldsm4(r0, r1, r2, r3, smem_u32(&Bl[buf][rowb][colb]));
                bl_[nt2 * 2][0] = r0; bl_[nt2 * 2][1] = r1;
                bl_[nt2 * 2 + 1][0] = r2; bl_[nt2 * 2 + 1][1] = r3;
            }
#pragma unroll
            for (int mf = 0; mf < 2; mf++)
#pragma unroll
                for (int nt = 0; nt < 4; nt++) {
                    mma16816(acc[mf][nt], ah[mf][0], ah[mf][1], ah[mf][2], ah[mf][3], bh_[nt][0], bh_[nt][1]);
                    mma16816(acc[mf][nt], ah[mf][0], ah[mf][1], ah[mf][2], ah[mf][3], bl_[nt][0], bl_[nt][1]);
                    if (!A_HALF)
                        mma16816(acc[mf][nt], al[mf][0], al[mf][1], al[mf][2], al[mf][3], bh_[nt][0], bh_[nt][1]);
                }
        }
        __syncthreads();
    }

    // ---- epilogue ----
#pragma unroll
    for (int mf = 0; mf < 2; mf++) {
        const int rlo = row0 + wm * 32 + mf * 16 + (lane >> 2);
#pragma unroll
        for (int nt = 0; nt < 4; nt++) {
            const int cc = col0 + wn * 32 + nt * 8 + (lane & 3) * 2;
#pragma unroll
            for (int half_ = 0; half_ < 2; half_++) {
                const int r = rlo + half_ * 8;
                const float v0 = acc[mf][nt][half_ * 2 + 0];
                const float v1 = acc[mf][nt][half_ * 2 + 1];
                if (MODE == 2) {
                    float2 o = make_float2(v0 + bias[cc], v1 + bias[cc + 1]);
                    *(float2*)&outf[(size_t)r * C_DIM + cc] = o;
                } else if (MODE == 0) {
                    const int b = r >> 9, n = r & 511, h = cc >> 5, d = cc & 31;
                    float2 o = make_float2(v0 + bias[cc], v1 + bias[cc + 1]);
                    *(float2*)&g_qf[(((size_t)(b * HEADS + h) << 9) | n) * HD + d] = o;
                } else { // MODE 1
                    const int b = r >> 9, n = r & 511;
                    if (cc < C_DIM) {
                        const int h = cc >> 5, d = cc & 31;
                        float2 o = make_float2(v0, v1);
                        *(float2*)&g_kf[(((size_t)(b * HEADS + h) << 9) | n) * HD + d] = o;
                    } else {
                        const int cv = cc - C_DIM, h = cv >> 5, d = cv & 31;
                        g_vt[((size_t)(b * HEADS + h) * HD + d) * SEQ + n]     = __float2half_rn(v0 + bias[cv]);
                        g_vt[((size_t)(b * HEADS + h) * HD + d + 1) * SEQ + n] = __float2half_rn(v1 + bias[cv + 1]);
                    }
                }
            }
        }
    }
}

// ============================================================
// Normalize q (x per-head scale) and k; emit split fp16.
// ============================================================
__global__ __launch_bounds__(256)
void norm_kernel(const float* __restrict__ ls)
{
    const int g = blockIdx.x * 256 + threadIdx.x;
    const int wid = g >> 5, lane = g & 31;
    const int row = wid * 8 + (lane >> 2);
    const int q4 = lane & 3;
    const bool is_q = row < BH * SEQ;
    const int rr = is_q ? row : row - BH * SEQ;

    const float* src = (is_q ? g_qf : g_kf) + (size_t)rr * HD + q4 * 8;
    float4 v0 = *(const float4*)&src[0];
    float4 v1 = *(const float4*)&src[4];
    float ss = v0.x * v0.x + v0.y * v0.y + v0.z * v0.z + v0.w * v0.w
             + v1.x * v1.x + v1.y * v1.y + v1.z * v1.z + v1.w * v1.w;
    ss += __shfl_xor_sync(0xffffffffu, ss, 1);
    ss += __shfl_xor_sync(0xffffffffu, ss, 2);
    float inv = 1.0f / fmaxf(sqrtf(ss), 1e-12f);
    if (is_q) {
        const int h = (rr >> 9) % HEADS;
        inv *= __expf(fminf(ls[h], LOGIT_MAX));
    }

    __half2 hi[4], lo[4];
    split2(v0.x * inv, v0.y * inv, hi[0], lo[0]);
    split2(v0.z * inv, v0.w * inv, hi[1], lo[1]);
    split2(v1.x * inv, v1.y * inv, hi[2], lo[2]);
    split2(v1.z * inv, v1.w * inv, hi[3], lo[3]);

    __half* dh = (is_q ? g_qh : g_kh) + (size_t)rr * HD + q4 * 8;
    __half* dl = (is_q ? g_ql : g_kl) + (size_t)rr * HD + q4 * 8;
    *(uint4*)dh = *(uint4*)hi;
    *(uint4*)dl = *(uint4*)lo;
}

// ============================================================
// FlashAttention-2 style per (b,h). 256 thr, 8 warps, 2 CTA/SM.
// K hi/lo in swizzled exact-64B-row smem; V^T padded.
// ============================================================
__device__ __forceinline__ unsigned kswz(int r, int cbytes) {
    return r * 64 + (cbytes ^ ((r & 6) * 8));
}

__global__ __launch_bounds__(256, 2)
void attn_kernel()
{
    extern __shared__ __half sm[];
    __half* Khs = sm;                    // 512 rows x 64B, swizzled
    __half* Kls = sm + 512 * 32;
    __half* Vts = sm + 2 * 512 * 32;     // [32][520]

    const int bh = blockIdx.x;
    const int b = bh / HEADS, h = bh % HEADS;
    const int tid = threadIdx.x, w = tid >> 5, lane = tid & 31;

    const __half* kh = g_kh + (size_t)bh * SEQ * HD;
    const __half* kl = g_kl + (size_t)bh * SEQ * HD;
    const __half* vt = g_vt + (size_t)bh * HD * SEQ;

#pragma unroll
    for (int p = 0; p < 8; p++) {
        const int idx = p * 256 + tid;
        const int r = idx >> 2, cb = (idx & 3) * 16;
        const unsigned off = kswz(r, cb);
        *(uint4*)((char*)Khs + off) = *(const uint4*)&kh[r * HD + cb / 2];
        *(uint4*)((char*)Kls + off) = *(const uint4*)&kl[r * HD + cb / 2];
    }
#pragma unroll
    for (int p = 0; p < 8; p++) {
        const int idx = p * 256 + tid;
        const int d = idx >> 6, c8 = (idx & 63) * 8;
        *(uint4*)&Vts[d * 520 + c8] = *(const uint4*)&vt[d * SEQ + c8];
    }
    __syncthreads();

    const __half* qh = g_qh + (size_t)bh * SEQ * HD;
    const __half* ql = g_ql + (size_t)bh * SEQ * HD;

    for (int mf = 0; mf < 4; mf++) {
        const int m0 = w * 64 + mf * 16;
        const int rlo = m0 + (lane >> 2);

        unsigned qhf[2][4], qlf[2][4];
#pragma unroll
        for (int kf = 0; kf < 2; kf++) {
            const int kb = kf * 16 + (lane & 3) * 2;
            qhf[kf][0] = *(const unsigned*)&qh[(size_t)rlo * HD + kb];
            qhf[kf][1] = *(const unsigned*)&qh[(size_t)(rlo + 8) * HD + kb];
            qhf[kf][2] = *(const unsigned*)&qh[(size_t)rlo * HD + kb + 8];
            qhf[kf][3] = *(const unsigned*)&qh[(size_t)(rlo + 8) * HD + kb + 8];
            qlf[kf][0] = *(const unsigned*)&ql[(size_t)rlo * HD + kb];
            qlf[kf][1] = *(const unsigned*)&ql[(size_t)(rlo + 8) * HD + kb];
            qlf[kf][2] = *(const unsigned*)&ql[(size_t)rlo * HD + kb + 8];
            qlf[kf][3] = *(const unsigned*)&ql[(size_t)(rlo + 8) * HD + kb + 8];
        }

        float O[4][4] = {};
        float m_lo = -1e30f, m_hi = -1e30f, l_lo = 0.f, l_hi = 0.f;

        for (int kc = 0; kc < 8; kc++) {
            float S[8][4] = {};
#pragma unroll
            for (int nt2 = 0; nt2 < 4; nt2++) {
                const int rowb = kc * 64 + nt2 * 16 + ((lane >> 4) << 3) + (lane & 7);
                const int colb2 = ((lane >> 3) & 1) * 16;   // bytes
#pragma unroll
                for (int kf = 0; kf < 2; kf++) {
                    const unsigned off = kswz(rowb, kf * 32 + colb2);
                    unsigned kh0, kh1, kh2, kh3, kl0, kl1, kl2, kl3;
                    ldsm4(kh0, kh1, kh2, kh3, smem_u32((char*)Khs + off));
                    ldsm4(kl0, kl1, kl2, kl3, smem_u32((char*)Kls + off));
                    float* SA = S[nt2 * 2];
                    float* SB = S[nt2 * 2 + 1];
                    mma16816(SA, qhf[kf][0], qhf[kf][1], qhf[kf][2], qhf[kf][3], kh0, kh1);
                    mma16816(SB, qhf[kf][0], qhf[kf][1], qhf[kf][2], qhf[kf][3], kh2, kh3);
                    mma16816(SA, qhf[kf][0], qhf[kf][1], qhf[kf][2], qhf[kf][3], kl0, kl1);
                    mma16816(SB, qhf[kf][0], qhf[kf][1], qhf[kf][2], qhf[kf][3], kl2, kl3);
                    mma16816(SA, qlf[kf][0], qlf[kf][1], qlf[kf][2], qlf[kf][3], kh0, kh1);
                    mma16816(SB, qlf[kf][0], qlf[kf][1], qlf[kf][2], qlf[kf][3], kh2, kh3);
                }
            }

            // ---- online softmax ----
            float mx_lo = -1e30f, mx_hi = -1e30f;
#pragma unroll
            for (int nt = 0; nt < 8; nt++) {
                mx_lo = fmaxf(mx_lo, fmaxf(S[nt][0], S[nt][1]));
                mx_hi = fmaxf(mx_hi, fmaxf(S[nt][2], S[nt][3]));
            }
            mx_lo = fmaxf(mx_lo, __shfl_xor_sync(0xffffffffu, mx_lo, 1));
            mx_lo = fmaxf(mx_lo, __shfl_xor_sync(0xffffffffu, mx_lo, 2));
            mx_hi = fmaxf(mx_hi, __shfl_xor_sync(0xffffffffu, mx_hi, 1));
            mx_hi = fmaxf(mx_hi, __shfl_xor_sync(0xffffffffu, mx_hi, 2));

            const float mn_lo = fmaxf(m_lo, mx_lo), mn_hi = fmaxf(m_hi, mx_hi);
            const float rs_lo = __expf(m_lo - mn_lo), rs_hi = __expf(m_hi - mn_hi);
            m_lo = mn_lo; m_hi = mn_hi;

            float s_lo = 0.f, s_hi = 0.f;
#pragma unroll
            for (int nt = 0; nt < 8; nt++) {
                S[nt][0] = __expf(S[nt][0] - mn_lo);
                S[nt][1] = __expf(S[nt][1] - mn_lo);
                S[nt][2] = __expf(S[nt][2] - mn_hi);
                S[nt][3] = __expf(S[nt][3] - mn_hi);
                s_lo += S[nt][0] + S[nt][1];
                s_hi += S[nt][2] + S[nt][3];
            }
            s_lo += __shfl_xor_sync(0xffffffffu, s_lo, 1);
            s_lo += __shfl_xor_sync(0xffffffffu, s_lo, 2);
            s_hi += __shfl_xor_sync(0xffffffffu, s_hi, 1);
            s_hi += __shfl_xor_sync(0xffffffffu, s_hi, 2);
            l_lo = l_lo * rs_lo + s_lo;
            l_hi = l_hi * rs_hi + s_hi;
#pragma unroll
            for (int dt = 0; dt < 4; dt++) {
                O[dt][0] *= rs_lo; O[dt][1] *= rs_lo;
                O[dt][2] *= rs_hi; O[dt][3] *= rs_hi;
            }

            // ---- PV ----
#pragma unroll
            for (int ks = 0; ks < 4; ks++) {
                const unsigned p0 = pack_h2(S[2 * ks][0], S[2 * ks][1]);
                const unsigned p1 = pack_h2(S[2 * ks][2], S[2 * ks][3]);
                const unsigned p2 = pack_h2(S[2 * ks + 1][0], S[2 * ks + 1][1]);
                const unsigned p3 = pack_h2(S[2 * ks + 1][2], S[2 * ks + 1][3]);
#pragma unroll
                for (int dt2 = 0; dt2 < 2; dt2++) {
                    const int rowd = dt2 * 16 + ((lane >> 4) << 3) + (lane & 7);
                    const int colk = kc * 64 + ks * 16 + ((lane >> 3) & 1) * 8;
                    unsigned v0, v1, v2, v3;
                    ldsm4(v0, v1, v2, v3, smem_u32(&Vts[rowd * 520 + colk]));
                    mma16816(O[dt2 * 2],     p0, p1, p2, p3, v0, v1);
                    mma16816(O[dt2 * 2 + 1], p0, p1, p2, p3, v2, v3);
                }
            }
        }

        // ---- write ----
        const float il_lo = 1.0f / l_lo, il_hi = 1.0f / l_hi;
#pragma unroll
        for (int dt = 0; dt < 4; dt++) {
            __half2 o_lo = __floats2half2_rn(O[dt][0] * il_lo, O[dt][1] * il_lo);
            __half2 o_hi = __floats2half2_rn(O[dt][2] * il_hi, O[dt][3] * il_hi);
            const size_t base = ((size_t)b * SEQ + rlo) * C_DIM + h * HD + dt * 8 + (lane & 3) * 2;
            *(__half2*)&g_attno[base] = o_lo;
            *(__half2*)&g_attno[base + (size_t)8 * C_DIM] = o_hi;
        }
    }
}

// ============================================================
// Launch
// ============================================================
extern "C" void kernel_launch(void* const* d_in, const int* in_sizes, int n_in,
                              void* d_out, int out_size)
{
    (void)in_sizes; (void)n_in; (void)out_size;
    const float* x1     = (const float*)d_in[0];
    const float* x2     = (const float*)d_in[1];
    const float* q_w    = (const float*)d_in[2];
    const float* q_b    = (const float*)d_in[3];
    const float* kv_w   = (const float*)d_in[4];
    const float* v_b    = (const float*)d_in[5];
    const float* ls     = (const float*)d_in[6];
    const float* proj_w = (const float*)d_in[7];
    const float* proj_b = (const float*)d_in[8];
    float* out = (float*)d_out;

    __half *x1h, *x1l, *x2h, *x2l, *wqh, *wql, *wkvh, *wkvl, *wph, *wpl, *attno;
    cudaGetSymbolAddress((void**)&x1h,  g_x1h);  cudaGetSymbolAddress((void**)&x1l,  g_x1l);
    cudaGetSymbolAddress((void**)&x2h,  g_x2h);  cudaGetSymbolAddress((void**)&x2l,  g_x2l);
    cudaGetSymbolAddress((void**)&wqh,  g_wqh);  cudaGetSymbolAddress((void**)&wql,  g_wql);
    cudaGetSymbolAddress((void**)&wkvh, g_wkvh); cudaGetSymbolAddress((void**)&wkvl, g_wkvl);
    cudaGetSymbolAddress((void**)&wph,  g_wph);  cudaGetSymbolAddress((void**)&wpl,  g_wpl);
    cudaGetSymbolAddress((void**)&attno, g_attno);

    const int nX8 = MROWS * C_DIM / 8;       // 1,572,864
    split_kernel<<<(nX8 + 255) / 256, 256>>>(x1, x1h, x1l, nX8);
    split_kernel<<<(nX8 + 255) / 256, 256>>>(x2, x2h, x2l, nX8);
    split_kernel<<<(C_DIM * C_DIM / 8 + 255) / 256, 256>>>(q_w, wqh, wql, C_DIM * C_DIM / 8);
    split_kernel<<<(2 * C_DIM * C_DIM / 8 + 255) / 256, 256>>>(kv_w, wkvh, wkvl, 2 * C_DIM * C_DIM / 8);
    split_kernel<<<(C_DIM * C_DIM / 8 + 255) / 256, 256>>>(proj_w, wph, wpl, C_DIM * C_DIM / 8);

    gemm_kernel<C_DIM, 0><<<dim3(C_DIM / 64, MROWS / 128), 256>>>(x1h, x1l, wqh, wql, q_b, nullptr);
    gemm_kernel<2 * C_DIM, 1><<<dim3(2 * C_DIM / 64, MROWS / 128), 256>>>(x2h, x2l, wkvh, wkvl, v_b, nullptr);

    norm_kernel<<<(2 * BH * SEQ * 4) / 256, 256>>>(ls);

    const int smem_bytes = (2 * 512 * 32 + 32 * 520) * (int)sizeof(__half); // 98816
    cudaFuncSetAttribute(attn_kernel, cudaFuncAttributeMaxDynamicSharedMemorySize, smem_bytes);
    attn_kernel<<<BH, 256, smem_bytes>>>();

    gemm_kernel<C_DIM, 2><<<dim3(C_DIM / 64, MROWS / 128), 256>>>(attno, nullptr, wph, wpl, proj_b, out);
}

// round 4
// speedup vs baseline: 4.3675x; 1.1328x over previous
#include <cuda_runtime.h>
#include <cuda_fp16.h>

#define C_DIM 192
#define HEADS 6
#define HD 32
#define BATCH 128
#define SEQ 512
#define MROWS (BATCH * SEQ)        // 65536
#define BH (BATCH * HEADS)         // 768
#define LOGIT_MAX 4.6051701859880914f

// ---------------- device-global scratch ----------------
__device__ __half g_qh[(size_t)BH * SEQ * HD];    // normalized*scale q, fp16, head-major
__device__ __half g_kh[(size_t)BH * SEQ * HD];    // normalized k hi
__device__ __half g_kl[(size_t)BH * SEQ * HD];    // normalized k lo
__device__ __half g_vt[(size_t)BH * HD * SEQ];    // v transposed per (b,h): [d][n]
__device__ __half g_attno[(size_t)MROWS * C_DIM];
// pre-split inputs / weights
__device__ __half g_x1h[(size_t)MROWS * C_DIM];
__device__ __half g_x1l[(size_t)MROWS * C_DIM];
__device__ __half g_x2h[(size_t)MROWS * C_DIM];
__device__ __half g_x2l[(size_t)MROWS * C_DIM];
__device__ __half g_wqh[C_DIM * C_DIM];
__device__ __half g_wql[C_DIM * C_DIM];
__device__ __half g_wkvh[2 * C_DIM * C_DIM];
__device__ __half g_wkvl[2 * C_DIM * C_DIM];
__device__ __half g_wph[C_DIM * C_DIM];
__device__ __half g_wpl[C_DIM * C_DIM];

// ---------------- helpers ----------------
__device__ __forceinline__ unsigned smem_u32(const void* p) {
    return (unsigned)__cvta_generic_to_shared(p);
}
__device__ __forceinline__ void ldsm4(unsigned& r0, unsigned& r1, unsigned& r2, unsigned& r3, unsigned a) {
    asm volatile("ldmatrix.sync.aligned.m8n8.x4.shared.b16 {%0,%1,%2,%3},[%4];\n"
                 : "=r"(r0), "=r"(r1), "=r"(r2), "=r"(r3) : "r"(a));
}
__device__ __forceinline__ void mma16816(float* c, unsigned a0, unsigned a1, unsigned a2, unsigned a3,
                                         unsigned b0, unsigned b1) {
    asm volatile("mma.sync.aligned.m16n8k16.row.col.f32.f16.f16.f32 "
                 "{%0,%1,%2,%3},{%4,%5,%6,%7},{%8,%9},{%0,%1,%2,%3};\n"
                 : "+f"(c[0]), "+f"(c[1]), "+f"(c[2]), "+f"(c[3])
                 : "r"(a0), "r"(a1), "r"(a2), "r"(a3), "r"(b0), "r"(b1));
}
__device__ __forceinline__ void split2(float x, float y, __half2& hi, __half2& lo) {
    __half hx = __float2half_rn(x), hy = __float2half_rn(y);
    hi = __halves2half2(hx, hy);
    lo = __floats2half2_rn(x - __half2float(hx), y - __half2float(hy));
}
__device__ __forceinline__ unsigned pack_h2(float a, float b) {
    __half2 t = __floats2half2_rn(a, b);
    return *(unsigned*)&t;
}
__device__ __forceinline__ void cpa16(void* s, const void* g) {
    asm volatile("cp.async.ca.shared.global [%0], [%1], 16;\n" :: "r"(smem_u32(s)), "l"(g));
}
__device__ __forceinline__ void cpa_commit() { asm volatile("cp.async.commit_group;\n"); }
__device__ __forceinline__ void cpa_wait1()  { asm volatile("cp.async.wait_group 1;\n"); }
__device__ __forceinline__ void cpa_wait0()  { asm volatile("cp.async.wait_group 0;\n"); }

// ============================================================
// Pre-split fp32 -> (hi, lo) fp16. 8 elems per thread.
// ============================================================
__global__ __launch_bounds__(256)
void split_kernel(const float* __restrict__ src, __half* __restrict__ hi,
                  __half* __restrict__ lo, int n8)
{
    const int i = blockIdx.x * 256 + threadIdx.x;
    if (i >= n8) return;
    const float4 a = *(const float4*)&src[(size_t)i * 8];
    const float4 b = *(const float4*)&src[(size_t)i * 8 + 4];
    __half2 h[4], l[4];
    split2(a.x, a.y, h[0], l[0]);
    split2(a.z, a.w, h[1], l[1]);
    split2(b.x, b.y, h[2], l[2]);
    split2(b.z, b.w, h[3], l[3]);
    *(uint4*)&hi[(size_t)i * 8] = *(uint4*)h;
    *(uint4*)&lo[(size_t)i * 8] = *(uint4*)l;
}

// ============================================================
// Tensor-core GEMM on pre-split operands, cp.async double buffer.
// BM=128, BN=64, BK=32, 256 thr, 8 warps (4m x 2n).
// MODE 0: 3-term; epilogue fuses +q_b, L2-norm, *exp(ls), -> g_qh fp16
// MODE 1: 3-term; k cols: L2-norm -> g_kh/g_kl split; v cols: +v_b -> g_vt^T
// MODE 2: A single half (attno), W split, 2-term -> d_out (+bias)
// ============================================================
template<int NC, int MODE>
__global__ __launch_bounds__(256)
void gemm_kernel(const __half* __restrict__ Ah_g, const __half* __restrict__ Al_g,
                 const __half* __restrict__ Wh_g, const __half* __restrict__ Wl_g,
                 const float* __restrict__ bias, const float* __restrict__ ls,
                 float* __restrict__ outf)
{
    constexpr bool A_HALF = (MODE == 2);
    __shared__ __half Ah[2][128][40];
    __shared__ __half Al[2][A_HALF ? 8 : 128][40];
    __shared__ __half Bh[2][64][40];
    __shared__ __half Bl[2][64][40];

    const int tid = threadIdx.x, w = tid >> 5, lane = tid & 31;
    const int wm = w >> 1, wn = w & 1;
    const int row0 = blockIdx.y * 128, col0 = blockIdx.x * 64;

    auto load_stage = [&](int s, int buf) {
        const int k0 = s * 32;
#pragma unroll
        for (int j = 0; j < 2; j++) {
            const int idx = j * 256 + tid;
            const int r = idx >> 2, c8 = (idx & 3) * 8;
            cpa16(&Ah[buf][r][c8], &Ah_g[(size_t)(row0 + r) * C_DIM + k0 + c8]);
            if (!A_HALF)
                cpa16(&Al[buf][r][c8], &Al_g[(size_t)(row0 + r) * C_DIM + k0 + c8]);
        }
        {
            const int r = tid >> 2, c8 = (tid & 3) * 8;
            cpa16(&Bh[buf][r][c8], &Wh_g[(size_t)(col0 + r) * C_DIM + k0 + c8]);
            cpa16(&Bl[buf][r][c8], &Wl_g[(size_t)(col0 + r) * C_DIM + k0 + c8]);
        }
    };

    float acc[2][4][4] = {};

    load_stage(0, 0);
    cpa_commit();

    for (int s = 0; s < 6; s++) {
        const int buf = s & 1;
        if (s < 5) { load_stage(s + 1, buf ^ 1); cpa_commit(); cpa_wait1(); }
        else       { cpa_wait0(); }
        __syncthreads();

#pragma unroll
        for (int kf = 0; kf < 2; kf++) {
            unsigned ah[2][4], al[2][4];
#pragma unroll
            for (int mf = 0; mf < 2; mf++) {
                unsigned a = smem_u32(&Ah[buf][wm * 32 + mf * 16 + (lane & 15)][kf * 16 + (lane >> 4) * 8]);
                ldsm4(ah[mf][0], ah[mf][1], ah[mf][2], ah[mf][3], a);
                if (!A_HALF) {
                    a = smem_u32(&Al[buf][wm * 32 + mf * 16 + (lane & 15)][kf * 16 + (lane >> 4) * 8]);
                    ldsm4(al[mf][0], al[mf][1], al[mf][2], al[mf][3], a);
                }
            }
            unsigned bh_[4][2], bl_[4][2];
#pragma unroll
            for (int nt2 = 0; nt2 < 2; nt2++) {
                const int rowb = wn * 32 + nt2 * 16 + ((lane >> 4) << 3) + (lane & 7);
                const int colb = kf * 16 + ((lane >> 3) & 1) * 8;
                unsigned r0, r1, r2, r3;
                ldsm4(r0, r1, r2, r3, smem_u32(&Bh[buf][rowb][colb]));
                bh_[nt2 * 2][0] = r0; bh_[nt2 * 2][1] = r1;
                bh_[nt2 * 2 + 1][0] = r2; bh_[nt2 * 2 + 1][1] = r3;
                ldsm4(r0, r1, r2, r3, smem_u32(&Bl[buf][rowb][colb]));
                bl_[nt2 * 2][0] = r0; bl_[nt2 * 2][1] = r1;
                bl_[nt2 * 2 + 1][0] = r2; bl_[nt2 * 2 + 1][1] = r3;
            }
#pragma unroll
            for (int mf = 0; mf < 2; mf++)
#pragma unroll
                for (int nt = 0; nt < 4; nt++) {
                    mma16816(acc[mf][nt], ah[mf][0], ah[mf][1], ah[mf][2], ah[mf][3], bh_[nt][0], bh_[nt][1]);
                    mma16816(acc[mf][nt], ah[mf][0], ah[mf][1], ah[mf][2], ah[mf][3], bl_[nt][0], bl_[nt][1]);
                    if (!A_HALF)
                        mma16816(acc[mf][nt], al[mf][0], al[mf][1], al[mf][2], al[mf][3], bh_[nt][0], bh_[nt][1]);
                }
        }
        __syncthreads();
    }

    // ---- epilogue ----
    if (MODE == 2) {
#pragma unroll
        for (int mf = 0; mf < 2; mf++) {
            const int rlo = row0 + wm * 32 + mf * 16 + (lane >> 2);
#pragma unroll
            for (int nt = 0; nt < 4; nt++) {
                const int cc = col0 + wn * 32 + nt * 8 + (lane & 3) * 2;
#pragma unroll
                for (int half_ = 0; half_ < 2; half_++) {
                    const int r = rlo + half_ * 8;
                    float2 o = make_float2(acc[mf][nt][half_ * 2 + 0] + bias[cc],
                                           acc[mf][nt][half_ * 2 + 1] + bias[cc + 1]);
                    *(float2*)&outf[(size_t)r * C_DIM + cc] = o;
                }
            }
        }
        return;
    }

    const int cbase = col0 + wn * 32;           // 32-aligned
    const bool is_v = (MODE == 1) && (cbase >= C_DIM);

    if (is_v) {
        // v columns: add v_b, write transposed fp16
#pragma unroll
        for (int mf = 0; mf < 2; mf++) {
            const int rlo = row0 + wm * 32 + mf * 16 + (lane >> 2);
#pragma unroll
            for (int nt = 0; nt < 4; nt++) {
                const int cv = cbase - C_DIM + nt * 8 + (lane & 3) * 2;
                const int h = cv >> 5, d = cv & 31;
#pragma unroll
                for (int half_ = 0; half_ < 2; half_++) {
                    const int r = rlo + half_ * 8;
                    const int b = r >> 9, n = r & 511;
                    const float v0 = acc[mf][nt][half_ * 2 + 0] + bias[cv];
                    const float v1 = acc[mf][nt][half_ * 2 + 1] + bias[cv + 1];
                    g_vt[((size_t)(b * HEADS + h) * HD + d) * SEQ + n]     = __float2half_rn(v0);
                    g_vt[((size_t)(b * HEADS + h) * HD + d + 1) * SEQ + n] = __float2half_rn(v1);
                }
            }
        }
        return;
    }

    // q or k columns: fused L2-normalize (+ per-head scale for q)
    const int h = cbase >> 5;
    float hsc = 1.0f;
    if (MODE == 0) hsc = __expf(fminf(ls[h], LOGIT_MAX));

#pragma unroll
    for (int mf = 0; mf < 2; mf++) {
        const int rlo = row0 + wm * 32 + mf * 16 + (lane >> 2);
        float va[4][4];
        float ss0 = 0.f, ss1 = 0.f;
#pragma unroll
        for (int nt = 0; nt < 4; nt++) {
            const int cc = cbase + nt * 8 + (lane & 3) * 2;
            float b0 = 0.f, b1 = 0.f;
            if (MODE == 0) { b0 = bias[cc]; b1 = bias[cc + 1]; }
            va[nt][0] = acc[mf][nt][0] + b0;
            va[nt][1] = acc[mf][nt][1] + b1;
            va[nt][2] = acc[mf][nt][2] + b0;
            va[nt][3] = acc[mf][nt][3] + b1;
            ss0 += va[nt][0] * va[nt][0] + va[nt][1] * va[nt][1];
            ss1 += va[nt][2] * va[nt][2] + va[nt][3] * va[nt][3];
        }
        ss0 += __shfl_xor_sync(0xffffffffu, ss0, 1);
        ss0 += __shfl_xor_sync(0xffffffffu, ss0, 2);
        ss1 += __shfl_xor_sync(0xffffffffu, ss1, 1);
        ss1 += __shfl_xor_sync(0xffffffffu, ss1, 2);
        const float inv0 = hsc / fmaxf(sqrtf(ss0), 1e-12f);
        const float inv1 = hsc / fmaxf(sqrtf(ss1), 1e-12f);

#pragma unroll
        for (int half_ = 0; half_ < 2; half_++) {
            const int r = rlo + half_ * 8;
            const int b = r >> 9, n = r & 511;
            const float inv = half_ ? inv1 : inv0;
            const size_t base = (((size_t)(b * HEADS + h) << 9) | n) * HD;
#pragma unroll
            for (int nt = 0; nt < 4; nt++) {
                const int d = nt * 8 + (lane & 3) * 2;
                const float v0 = va[nt][half_ * 2 + 0] * inv;
                const float v1 = va[nt][half_ * 2 + 1] * inv;
                if (MODE == 0) {
                    *(__half2*)&g_qh[base + d] = __floats2half2_rn(v0, v1);
                } else {
                    __half2 hi, lo;
                    split2(v0, v1, hi, lo);
                    *(__half2*)&g_kh[base + d] = hi;
                    *(__half2*)&g_kl[base + d] = lo;
                }
            }
        }
    }
}

// ============================================================
// FlashAttention-2 style per (b,h). 256 thr, 8 warps, 2 CTA/SM.
// Q single fp16; K split hi/lo in swizzled smem; V^T padded.
// QK^T = qh*kh + qh*kl (2-term).
// ============================================================
__device__ __forceinline__ unsigned kswz(int r, int cbytes) {
    return r * 64 + (cbytes ^ ((r & 6) * 8));
}

__global__ __launch_bounds__(256, 2)
void attn_kernel()
{
    extern __shared__ __half sm[];
    __half* Khs = sm;                    // 512 rows x 64B, swizzled
    __half* Kls = sm + 512 * 32;
    __half* Vts = sm + 2 * 512 * 32;     // [32][520]

    const int bh = blockIdx.x;
    const int b = bh / HEADS, h = bh % HEADS;
    const int tid = threadIdx.x, w = tid >> 5, lane = tid & 31;

    const __half* kh = g_kh + (size_t)bh * SEQ * HD;
    const __half* kl = g_kl + (size_t)bh * SEQ * HD;
    const __half* vt = g_vt + (size_t)bh * HD * SEQ;

#pragma unroll
    for (int p = 0; p < 8; p++) {
        const int idx = p * 256 + tid;
        const int r = idx >> 2, cb = (idx & 3) * 16;
        const unsigned off = kswz(r, cb);
        *(uint4*)((char*)Khs + off) = *(const uint4*)&kh[r * HD + cb / 2];
        *(uint4*)((char*)Kls + off) = *(const uint4*)&kl[r * HD + cb / 2];
    }
#pragma unroll
    for (int p = 0; p < 8; p++) {
        const int idx = p * 256 + tid;
        const int d = idx >> 6, c8 = (idx & 63) * 8;
        *(uint4*)&Vts[d * 520 + c8] = *(const uint4*)&vt[d * SEQ + c8];
    }
    __syncthreads();

    const __half* qh = g_qh + (size_t)bh * SEQ * HD;

    for (int mf = 0; mf < 4; mf++) {
        const int m0 = w * 64 + mf * 16;
        const int rlo = m0 + (lane >> 2);

        unsigned qhf[2][4];
#pragma unroll
        for (int kf = 0; kf < 2; kf++) {
            const int kb = kf * 16 + (lane & 3) * 2;
            qhf[kf][0] = *(const unsigned*)&qh[(size_t)rlo * HD + kb];
            qhf[kf][1] = *(const unsigned*)&qh[(size_t)(rlo + 8) * HD + kb];
            qhf[kf][2] = *(const unsigned*)&qh[(size_t)rlo * HD + kb + 8];
            qhf[kf][3] = *(const unsigned*)&qh[(size_t)(rlo + 8) * HD + kb + 8];
        }

        float O[4][4] = {};
        float m_lo = -1e30f, m_hi = -1e30f, l_lo = 0.f, l_hi = 0.f;

        for (int kc = 0; kc < 8; kc++) {
            float S[8][4] = {};
#pragma unroll
            for (int nt2 = 0; nt2 < 4; nt2++) {
                const int rowb = kc * 64 + nt2 * 16 + ((lane >> 4) << 3) + (lane & 7);
                const int colb2 = ((lane >> 3) & 1) * 16;   // bytes
#pragma unroll
                for (int kf = 0; kf < 2; kf++) {
                    const unsigned off = kswz(rowb, kf * 32 + colb2);
                    unsigned kh0, kh1, kh2, kh3, kl0, kl1, kl2, kl3;
                    ldsm4(kh0, kh1, kh2, kh3, smem_u32((char*)Khs + off));
                    ldsm4(kl0, kl1, kl2, kl3, smem_u32((char*)Kls + off));
                    float* SA = S[nt2 * 2];
                    float* SB = S[nt2 * 2 + 1];
                    mma16816(SA, qhf[kf][0], qhf[kf][1], qhf[kf][2], qhf[kf][3], kh0, kh1);
                    mma16816(SB, qhf[kf][0], qhf[kf][1], qhf[kf][2], qhf[kf][3], kh2, kh3);
                    mma16816(SA, qhf[kf][0], qhf[kf][1], qhf[kf][2], qhf[kf][3], kl0, kl1);
                    mma16816(SB, qhf[kf][0], qhf[kf][1], qhf[kf][2], qhf[kf][3], kl2, kl3);
                }
            }

            // ---- online softmax ----
            float mx_lo = -1e30f, mx_hi = -1e30f;
#pragma unroll
            for (int nt = 0; nt < 8; nt++) {
                mx_lo = fmaxf(mx_lo, fmaxf(S[nt][0], S[nt][1]));
                mx_hi = fmaxf(mx_hi, fmaxf(S[nt][2], S[nt][3]));
            }
            mx_lo = fmaxf(mx_lo, __shfl_xor_sync(0xffffffffu, mx_lo, 1));
            mx_lo = fmaxf(mx_lo, __shfl_xor_sync(0xffffffffu, mx_lo, 2));
            mx_hi = fmaxf(mx_hi, __shfl_xor_sync(0xffffffffu, mx_hi, 1));
            mx_hi = fmaxf(mx_hi, __shfl_xor_sync(0xffffffffu, mx_hi, 2));

            const float mn_lo = fmaxf(m_lo, mx_lo), mn_hi = fmaxf(m_hi, mx_hi);
            const float rs_lo = __expf(m_lo - mn_lo), rs_hi = __expf(m_hi - mn_hi);
            m_lo = mn_lo; m_hi = mn_hi;

            float s_lo = 0.f, s_hi = 0.f;
#pragma unroll
            for (int nt = 0; nt < 8; nt++) {
                S[nt][0] = __expf(S[nt][0] - mn_lo);
                S[nt][1] = __expf(S[nt][1] - mn_lo);
                S[nt][2] = __expf(S[nt][2] - mn_hi);
                S[nt][3] = __expf(S[nt][3] - mn_hi);
                s_lo += S[nt][0] + S[nt][1];
                s_hi += S[nt][2] + S[nt][3];
            }
            s_lo += __shfl_xor_sync(0xffffffffu, s_lo, 1);
            s_lo += __shfl_xor_sync(0xffffffffu, s_lo, 2);
            s_hi += __shfl_xor_sync(0xffffffffu, s_hi, 1);
            s_hi += __shfl_xor_sync(0xffffffffu, s_hi, 2);
            l_lo = l_lo * rs_lo + s_lo;
            l_hi = l_hi * rs_hi + s_hi;
#pragma unroll
            for (int dt = 0; dt < 4; dt++) {
                O[dt][0] *= rs_lo; O[dt][1] *= rs_lo;
                O[dt][2] *= rs_hi; O[dt][3] *= rs_hi;
            }

            // ---- PV ----
#pragma unroll
            for (int ks = 0; ks < 4; ks++) {
                const unsigned p0 = pack_h2(S[2 * ks][0], S[2 * ks][1]);
                const unsigned p1 = pack_h2(S[2 * ks][2], S[2 * ks][3]);
                const unsigned p2 = pack_h2(S[2 * ks + 1][0], S[2 * ks + 1][1]);
                const unsigned p3 = pack_h2(S[2 * ks + 1][2], S[2 * ks + 1][3]);
#pragma unroll
                for (int dt2 = 0; dt2 < 2; dt2++) {
                    const int rowd = dt2 * 16 + ((lane >> 4) << 3) + (lane & 7);
                    const int colk = kc * 64 + ks * 16 + ((lane >> 3) & 1) * 8;
                    unsigned v0, v1, v2, v3;
                    ldsm4(v0, v1, v2, v3, smem_u32(&Vts[rowd * 520 + colk]));
                    mma16816(O[dt2 * 2],     p0, p1, p2, p3, v0, v1);
                    mma16816(O[dt2 * 2 + 1], p0, p1, p2, p3, v2, v3);
                }
            }
        }

        // ---- write ----
        const float il_lo = 1.0f / l_lo, il_hi = 1.0f / l_hi;
#pragma unroll
        for (int dt = 0; dt < 4; dt++) {
            __half2 o_lo = __floats2half2_rn(O[dt][0] * il_lo, O[dt][1] * il_lo);
            __half2 o_hi = __floats2half2_rn(O[dt][2] * il_hi, O[dt][3] * il_hi);
            const size_t base = ((size_t)b * SEQ + rlo) * C_DIM + h * HD + dt * 8 + (lane & 3) * 2;
            *(__half2*)&g_attno[base] = o_lo;
            *(__half2*)&g_attno[base + (size_t)8 * C_DIM] = o_hi;
        }
    }
}

// ============================================================
// Launch
// ============================================================
extern "C" void kernel_launch(void* const* d_in, const int* in_sizes, int n_in,
                              void* d_out, int out_size)
{
    (void)in_sizes; (void)n_in; (void)out_size;
    const float* x1     = (const float*)d_in[0];
    const float* x2     = (const float*)d_in[1];
    const float* q_w    = (const float*)d_in[2];
    const float* q_b    = (const float*)d_in[3];
    const float* kv_w   = (const float*)d_in[4];
    const float* v_b    = (const float*)d_in[5];
    const float* ls     = (const float*)d_in[6];
    const float* proj_w = (const float*)d_in[7];
    const float* proj_b = (const float*)d_in[8];
    float* out = (float*)d_out;

    __half *x1h, *x1l, *x2h, *x2l, *wqh, *wql, *wkvh, *wkvl, *wph, *wpl, *attno;
    cudaGetSymbolAddress((void**)&x1h,  g_x1h);  cudaGetSymbolAddress((void**)&x1l,  g_x1l);
    cudaGetSymbolAddress((void**)&x2h,  g_x2h);  cudaGetSymbolAddress((void**)&x2l,  g_x2l);
    cudaGetSymbolAddress((void**)&wqh,  g_wqh);  cudaGetSymbolAddress((void**)&wql,  g_wql);
    cudaGetSymbolAddress((void**)&wkvh, g_wkvh); cudaGetSymbolAddress((void**)&wkvl, g_wkvl);
    cudaGetSymbolAddress((void**)&wph,  g_wph);  cudaGetSymbolAddress((void**)&wpl,  g_wpl);
    cudaGetSymbolAddress((void**)&attno, g_attno);

    const int nX8 = MROWS * C_DIM / 8;
    split_kernel<<<(nX8 + 255) / 256, 256>>>(x1, x1h, x1l, nX8);
    split_kernel<<<(nX8 + 255) / 256, 256>>>(x2, x2h, x2l, nX8);
    split_kernel<<<(C_DIM * C_DIM / 8 + 255) / 256, 256>>>(q_w, wqh, wql, C_DIM * C_DIM / 8);
    split_kernel<<<(2 * C_DIM * C_DIM / 8 + 255) / 256, 256>>>(kv_w, wkvh, wkvl, 2 * C_DIM * C_DIM / 8);
    split_kernel<<<(C_DIM * C_DIM / 8 + 255) / 256, 256>>>(proj_w, wph, wpl, C_DIM * C_DIM / 8);

    // q projection + fused normalize/scale -> g_qh
    gemm_kernel<C_DIM, 0><<<dim3(C_DIM / 64, MROWS / 128), 256>>>(x1h, x1l, wqh, wql, q_b, ls, nullptr);
    // kv projection + fused k-normalize/split -> g_kh/g_kl; v -> g_vt
    gemm_kernel<2 * C_DIM, 1><<<dim3(2 * C_DIM / 64, MROWS / 128), 256>>>(x2h, x2l, wkvh, wkvl, v_b, nullptr, nullptr);

    const int smem_bytes = (2 * 512 * 32 + 32 * 520) * (int)sizeof(__half); // 98816
    cudaFuncSetAttribute(attn_kernel, cudaFuncAttributeMaxDynamicSharedMemorySize, smem_bytes);
    attn_kernel<<<BH, 256, smem_bytes>>>();

    gemm_kernel<C_DIM, 2><<<dim3(C_DIM / 64, MROWS / 128), 256>>>(attno, nullptr, wph, wpl, proj_b, nullptr, out);
}

// round 5
// speedup vs baseline: 5.2060x; 1.1920x over previous
#include <cuda_runtime.h>
#include <cuda_fp16.h>

#define C_DIM 192
#define HEADS 6
#define HD 32
#define BATCH 128
#define SEQ 512
#define MROWS (BATCH * SEQ)        // 65536
#define BH (BATCH * HEADS)         // 768
#define LOGIT_MAX 4.6051701859880914f

// ---------------- device-global scratch ----------------
__device__ __half g_qh[(size_t)BH * SEQ * HD];    // normalized*scale q, fp16, head-major
__device__ __half g_kh[(size_t)BH * SEQ * HD];    // normalized k, fp16
__device__ __half g_vt[(size_t)BH * HD * SEQ];    // v transposed per (b,h): [d][n]
__device__ __half g_attno[(size_t)MROWS * C_DIM];
// pre-split / converted inputs & weights
__device__ __half g_x1h[(size_t)MROWS * C_DIM];
__device__ __half g_x2h[(size_t)MROWS * C_DIM];
__device__ __half g_x2l[(size_t)MROWS * C_DIM];
__device__ __half g_wqh[C_DIM * C_DIM];
__device__ __half g_wql[C_DIM * C_DIM];
__device__ __half g_wkvh[2 * C_DIM * C_DIM];
__device__ __half g_wkvl[2 * C_DIM * C_DIM];
__device__ __half g_wph[C_DIM * C_DIM];
__device__ __half g_wpl[C_DIM * C_DIM];

// ---------------- helpers ----------------
__device__ __forceinline__ unsigned smem_u32(const void* p) {
    return (unsigned)__cvta_generic_to_shared(p);
}
__device__ __forceinline__ void ldsm4(unsigned& r0, unsigned& r1, unsigned& r2, unsigned& r3, unsigned a) {
    asm volatile("ldmatrix.sync.aligned.m8n8.x4.shared.b16 {%0,%1,%2,%3},[%4];\n"
                 : "=r"(r0), "=r"(r1), "=r"(r2), "=r"(r3) : "r"(a));
}
__device__ __forceinline__ void mma16816(float* c, unsigned a0, unsigned a1, unsigned a2, unsigned a3,
                                         unsigned b0, unsigned b1) {
    asm volatile("mma.sync.aligned.m16n8k16.row.col.f32.f16.f16.f32 "
                 "{%0,%1,%2,%3},{%4,%5,%6,%7},{%8,%9},{%0,%1,%2,%3};\n"
                 : "+f"(c[0]), "+f"(c[1]), "+f"(c[2]), "+f"(c[3])
                 : "r"(a0), "r"(a1), "r"(a2), "r"(a3), "r"(b0), "r"(b1));
}
__device__ __forceinline__ void split2(float x, float y, __half2& hi, __half2& lo) {
    __half hx = __float2half_rn(x), hy = __float2half_rn(y);
    hi = __halves2half2(hx, hy);
    lo = __floats2half2_rn(x - __half2float(hx), y - __half2float(hy));
}
__device__ __forceinline__ unsigned pack_h2(float a, float b) {
    __half2 t = __floats2half2_rn(a, b);
    return *(unsigned*)&t;
}
__device__ __forceinline__ void cpa16(void* s, const void* g) {
    asm volatile("cp.async.ca.shared.global [%0], [%1], 16;\n" :: "r"(smem_u32(s)), "l"(g));
}
__device__ __forceinline__ void cpa_commit() { asm volatile("cp.async.commit_group;\n"); }
__device__ __forceinline__ void cpa_wait1()  { asm volatile("cp.async.wait_group 1;\n"); }
__device__ __forceinline__ void cpa_wait0()  { asm volatile("cp.async.wait_group 0;\n"); }

// ============================================================
// fp32 -> (hi, lo) fp16 split. 8 elems per thread.
// ============================================================
__global__ __launch_bounds__(256)
void split_kernel(const float* __restrict__ src, __half* __restrict__ hi,
                  __half* __restrict__ lo, int n8)
{
    const int i = blockIdx.x * 256 + threadIdx.x;
    if (i >= n8) return;
    const float4 a = *(const float4*)&src[(size_t)i * 8];
    const float4 b = *(const float4*)&src[(size_t)i * 8 + 4];
    __half2 h[4], l[4];
    split2(a.x, a.y, h[0], l[0]);
    split2(a.z, a.w, h[1], l[1]);
    split2(b.x, b.y, h[2], l[2]);
    split2(b.z, b.w, h[3], l[3]);
    *(uint4*)&hi[(size_t)i * 8] = *(uint4*)h;
    *(uint4*)&lo[(size_t)i * 8] = *(uint4*)l;
}

// fp32 -> fp16 (hi only). 8 elems per thread.
__global__ __launch_bounds__(256)
void tohalf_kernel(const float* __restrict__ src, __half* __restrict__ hi, int n8)
{
    const int i = blockIdx.x * 256 + threadIdx.x;
    if (i >= n8) return;
    const float4 a = *(const float4*)&src[(size_t)i * 8];
    const float4 b = *(const float4*)&src[(size_t)i * 8 + 4];
    __half2 h[4];
    h[0] = __floats2half2_rn(a.x, a.y);
    h[1] = __floats2half2_rn(a.z, a.w);
    h[2] = __floats2half2_rn(b.x, b.y);
    h[3] = __floats2half2_rn(b.z, b.w);
    *(uint4*)&hi[(size_t)i * 8] = *(uint4*)h;
}

// ============================================================
// Tensor-core GEMM, cp.async double buffer.
// BM=128, BN=64, BK=32, 256 thr, 8 warps (4m x 2n).
// MODE 0: A single half (x1h), W split, 2-term;
//         epilogue: +q_b, L2-norm, *exp(ls) -> g_qh fp16
// MODE 1: A split (x2 hi/lo), W split, 3-term;
//         k cols: L2-norm -> g_kh fp16; v cols: +v_b -> g_vt^T fp16
// MODE 2: A single half (attno), W split, 2-term -> d_out fp32 (+bias)
// ============================================================
template<int NC, int MODE>
__global__ __launch_bounds__(256)
void gemm_kernel(const __half* __restrict__ Ah_g, const __half* __restrict__ Al_g,
                 const __half* __restrict__ Wh_g, const __half* __restrict__ Wl_g,
                 const float* __restrict__ bias, const float* __restrict__ ls,
                 float* __restrict__ outf)
{
    constexpr bool A_HALF = (MODE != 1);
    __shared__ __half Ah[2][128][40];
    __shared__ __half Al[2][A_HALF ? 8 : 128][40];
    __shared__ __half Bh[2][64][40];
    __shared__ __half Bl[2][64][40];

    const int tid = threadIdx.x, w = tid >> 5, lane = tid & 31;
    const int wm = w >> 1, wn = w & 1;
    const int row0 = blockIdx.y * 128, col0 = blockIdx.x * 64;

    auto load_stage = [&](int s, int buf) {
        const int k0 = s * 32;
#pragma unroll
        for (int j = 0; j < 2; j++) {
            const int idx = j * 256 + tid;
            const int r = idx >> 2, c8 = (idx & 3) * 8;
            cpa16(&Ah[buf][r][c8], &Ah_g[(size_t)(row0 + r) * C_DIM + k0 + c8]);
            if (!A_HALF)
                cpa16(&Al[buf][r][c8], &Al_g[(size_t)(row0 + r) * C_DIM + k0 + c8]);
        }
        {
            const int r = tid >> 2, c8 = (tid & 3) * 8;
            cpa16(&Bh[buf][r][c8], &Wh_g[(size_t)(col0 + r) * C_DIM + k0 + c8]);
            cpa16(&Bl[buf][r][c8], &Wl_g[(size_t)(col0 + r) * C_DIM + k0 + c8]);
        }
    };

    float acc[2][4][4] = {};

    load_stage(0, 0);
    cpa_commit();

    for (int s = 0; s < 6; s++) {
        const int buf = s & 1;
        if (s < 5) { load_stage(s + 1, buf ^ 1); cpa_commit(); cpa_wait1(); }
        else       { cpa_wait0(); }
        __syncthreads();

#pragma unroll
        for (int kf = 0; kf < 2; kf++) {
            unsigned ah[2][4], al[2][4];
#pragma unroll
            for (int mf = 0; mf < 2; mf++) {
                unsigned a = smem_u32(&Ah[buf][wm * 32 + mf * 16 + (lane & 15)][kf * 16 + (lane >> 4) * 8]);
                ldsm4(ah[mf][0], ah[mf][1], ah[mf][2], ah[mf][3], a);
                if (!A_HALF) {
                    a = smem_u32(&Al[buf][wm * 32 + mf * 16 + (lane & 15)][kf * 16 + (lane >> 4) * 8]);
                    ldsm4(al[mf][0], al[mf][1], al[mf][2], al[mf][3], a);
                }
            }
            unsigned bh_[4][2], bl_[4][2];
#pragma unroll
            for (int nt2 = 0; nt2 < 2; nt2++) {
                const int rowb = wn * 32 + nt2 * 16 + ((lane >> 4) << 3) + (lane & 7);
                const int colb = kf * 16 + ((lane >> 3) & 1) * 8;
                unsigned r0, r1, r2, r3;
                ldsm4(r0, r1, r2, r3, smem_u32(&Bh[buf][rowb][colb]));
                bh_[nt2 * 2][0] = r0; bh_[nt2 * 2][1] = r1;
                bh_[nt2 * 2 + 1][0] = r2; bh_[nt2 * 2 + 1][1] = r3;
                ldsm4(r0, r1, r2, r3, smem_u32(&Bl[buf][rowb][colb]));
                bl_[nt2 * 2][0] = r0; bl_[nt2 * 2][1] = r1;
                bl_[nt2 * 2 + 1][0] = r2; bl_[nt2 * 2 + 1][1] = r3;
            }
#pragma unroll
            for (int mf = 0; mf < 2; mf++)
#pragma unroll
                for (int nt = 0; nt < 4; nt++) {
                    mma16816(acc[mf][nt], ah[mf][0], ah[mf][1], ah[mf][2], ah[mf][3], bh_[nt][0], bh_[nt][1]);
                    mma16816(acc[mf][nt], ah[mf][0], ah[mf][1], ah[mf][2], ah[mf][3], bl_[nt][0], bl_[nt][1]);
                    if (!A_HALF)
                        mma16816(acc[mf][nt], al[mf][0], al[mf][1], al[mf][2], al[mf][3], bh_[nt][0], bh_[nt][1]);
                }
        }
        __syncthreads();
    }

    // ---- epilogue ----
    if (MODE == 2) {
#pragma unroll
        for (int mf = 0; mf < 2; mf++) {
            const int rlo = row0 + wm * 32 + mf * 16 + (lane >> 2);
#pragma unroll
            for (int nt = 0; nt < 4; nt++) {
                const int cc = col0 + wn * 32 + nt * 8 + (lane & 3) * 2;
#pragma unroll
                for (int half_ = 0; half_ < 2; half_++) {
                    const int r = rlo + half_ * 8;
                    float2 o = make_float2(acc[mf][nt][half_ * 2 + 0] + bias[cc],
                                           acc[mf][nt][half_ * 2 + 1] + bias[cc + 1]);
                    *(float2*)&outf[(size_t)r * C_DIM + cc] = o;
                }
            }
        }
        return;
    }

    const int cbase = col0 + wn * 32;           // 32-aligned
    const bool is_v = (MODE == 1) && (cbase >= C_DIM);

    if (is_v) {
#pragma unroll
        for (int mf = 0; mf < 2; mf++) {
            const int rlo = row0 + wm * 32 + mf * 16 + (lane >> 2);
#pragma unroll
            for (int nt = 0; nt < 4; nt++) {
                const int cv = cbase - C_DIM + nt * 8 + (lane & 3) * 2;
                const int h = cv >> 5, d = cv & 31;
#pragma unroll
                for (int half_ = 0; half_ < 2; half_++) {
                    const int r = rlo + half_ * 8;
                    const int b = r >> 9, n = r & 511;
                    const float v0 = acc[mf][nt][half_ * 2 + 0] + bias[cv];
                    const float v1 = acc[mf][nt][half_ * 2 + 1] + bias[cv + 1];
                    g_vt[((size_t)(b * HEADS + h) * HD + d) * SEQ + n]     = __float2half_rn(v0);
                    g_vt[((size_t)(b * HEADS + h) * HD + d + 1) * SEQ + n] = __float2half_rn(v1);
                }
            }
        }
        return;
    }

    // q or k columns: fused L2-normalize (+ per-head scale for q)
    const int h = cbase >> 5;
    float hsc = 1.0f;
    if (MODE == 0) hsc = __expf(fminf(ls[h], LOGIT_MAX));

#pragma unroll
    for (int mf = 0; mf < 2; mf++) {
        const int rlo = row0 + wm * 32 + mf * 16 + (lane >> 2);
        float va[4][4];
        float ss0 = 0.f, ss1 = 0.f;
#pragma unroll
        for (int nt = 0; nt < 4; nt++) {
            const int cc = cbase + nt * 8 + (lane & 3) * 2;
            float b0 = 0.f, b1 = 0.f;
            if (MODE == 0) { b0 = bias[cc]; b1 = bias[cc + 1]; }
            va[nt][0] = acc[mf][nt][0] + b0;
            va[nt][1] = acc[mf][nt][1] + b1;
            va[nt][2] = acc[mf][nt][2] + b0;
            va[nt][3] = acc[mf][nt][3] + b1;
            ss0 += va[nt][0] * va[nt][0] + va[nt][1] * va[nt][1];
            ss1 += va[nt][2] * va[nt][2] + va[nt][3] * va[nt][3];
        }
        ss0 += __shfl_xor_sync(0xffffffffu, ss0, 1);
        ss0 += __shfl_xor_sync(0xffffffffu, ss0, 2);
        ss1 += __shfl_xor_sync(0xffffffffu, ss1, 1);
        ss1 += __shfl_xor_sync(0xffffffffu, ss1, 2);
        const float inv0 = hsc / fmaxf(sqrtf(ss0), 1e-12f);
        const float inv1 = hsc / fmaxf(sqrtf(ss1), 1e-12f);

#pragma unroll
        for (int half_ = 0; half_ < 2; half_++) {
            const int r = rlo + half_ * 8;
            const int b = r >> 9, n = r & 511;
            const float inv = half_ ? inv1 : inv0;
            const size_t base = (((size_t)(b * HEADS + h) << 9) | n) * HD;
#pragma unroll
            for (int nt = 0; nt < 4; nt++) {
                const int d = nt * 8 + (lane & 3) * 2;
                const float v0 = va[nt][half_ * 2 + 0] * inv;
                const float v1 = va[nt][half_ * 2 + 1] * inv;
                __half* dst = (MODE == 0) ? g_qh : g_kh;
                *(__half2*)&dst[base + d] = __floats2half2_rn(v0, v1);
            }
        }
    }
}

// ============================================================
// FlashAttention-2 style per (b,h). 256 thr, 8 warps, 3 CTA/SM.
// Q, K single fp16 (K in swizzled smem); V^T padded.
// ============================================================
__device__ __forceinline__ unsigned kswz(int r, int cbytes) {
    return r * 64 + (cbytes ^ ((r & 6) * 8));
}

__global__ __launch_bounds__(256, 3)
void attn_kernel()
{
    extern __shared__ __half sm[];
    __half* Khs = sm;                    // 512 rows x 64B, swizzled
    __half* Vts = sm + 512 * 32;         // [32][520]

    const int bh = blockIdx.x;
    const int b = bh / HEADS, h = bh % HEADS;
    const int tid = threadIdx.x, w = tid >> 5, lane = tid & 31;

    const __half* kh = g_kh + (size_t)bh * SEQ * HD;
    const __half* vt = g_vt + (size_t)bh * HD * SEQ;

#pragma unroll
    for (int p = 0; p < 8; p++) {
        const int idx = p * 256 + tid;
        const int r = idx >> 2, cb = (idx & 3) * 16;
        *(uint4*)((char*)Khs + kswz(r, cb)) = *(const uint4*)&kh[r * HD + cb / 2];
    }
#pragma unroll
    for (int p = 0; p < 8; p++) {
        const int idx = p * 256 + tid;
        const int d = idx >> 6, c8 = (idx & 63) * 8;
        *(uint4*)&Vts[d * 520 + c8] = *(const uint4*)&vt[d * SEQ + c8];
    }
    __syncthreads();

    const __half* qh = g_qh + (size_t)bh * SEQ * HD;

    for (int mf = 0; mf < 4; mf++) {
        const int m0 = w * 64 + mf * 16;
        const int rlo = m0 + (lane >> 2);

        unsigned qhf[2][4];
#pragma unroll
        for (int kf = 0; kf < 2; kf++) {
            const int kb = kf * 16 + (lane & 3) * 2;
            qhf[kf][0] = *(const unsigned*)&qh[(size_t)rlo * HD + kb];
            qhf[kf][1] = *(const unsigned*)&qh[(size_t)(rlo + 8) * HD + kb];
            qhf[kf][2] = *(const unsigned*)&qh[(size_t)rlo * HD + kb + 8];
            qhf[kf][3] = *(const unsigned*)&qh[(size_t)(rlo + 8) * HD + kb + 8];
        }

        float O[4][4] = {};
        float m_lo = -1e30f, m_hi = -1e30f, l_lo = 0.f, l_hi = 0.f;

        for (int kc = 0; kc < 8; kc++) {
            float S[8][4] = {};
#pragma unroll
            for (int nt2 = 0; nt2 < 4; nt2++) {
                const int rowb = kc * 64 + nt2 * 16 + ((lane >> 4) << 3) + (lane & 7);
                const int colb2 = ((lane >> 3) & 1) * 16;   // bytes
#pragma unroll
                for (int kf = 0; kf < 2; kf++) {
                    const unsigned off = kswz(rowb, kf * 32 + colb2);
                    unsigned kh0, kh1, kh2, kh3;
                    ldsm4(kh0, kh1, kh2, kh3, smem_u32((char*)Khs + off));
                    mma16816(S[nt2 * 2],     qhf[kf][0], qhf[kf][1], qhf[kf][2], qhf[kf][3], kh0, kh1);
                    mma16816(S[nt2 * 2 + 1], qhf[kf][0], qhf[kf][1], qhf[kf][2], qhf[kf][3], kh2, kh3);
                }
            }

            // ---- online softmax ----
            float mx_lo = -1e30f, mx_hi = -1e30f;
#pragma unroll
            for (int nt = 0; nt < 8; nt++) {
                mx_lo = fmaxf(mx_lo, fmaxf(S[nt][0], S[nt][1]));
                mx_hi = fmaxf(mx_hi, fmaxf(S[nt][2], S[nt][3]));
            }
            mx_lo = fmaxf(mx_lo, __shfl_xor_sync(0xffffffffu, mx_lo, 1));
            mx_lo = fmaxf(mx_lo, __shfl_xor_sync(0xffffffffu, mx_lo, 2));
            mx_hi = fmaxf(mx_hi, __shfl_xor_sync(0xffffffffu, mx_hi, 1));
            mx_hi = fmaxf(mx_hi, __shfl_xor_sync(0xffffffffu, mx_hi, 2));

            const float mn_lo = fmaxf(m_lo, mx_lo), mn_hi = fmaxf(m_hi, mx_hi);
            const float rs_lo = __expf(m_lo - mn_lo), rs_hi = __expf(m_hi - mn_hi);
            m_lo = mn_lo; m_hi = mn_hi;

            float s_lo = 0.f, s_hi = 0.f;
#pragma unroll
            for (int nt = 0; nt < 8; nt++) {
                S[nt][0] = __expf(S[nt][0] - mn_lo);
                S[nt][1] = __expf(S[nt][1] - mn_lo);
                S[nt][2] = __expf(S[nt][2] - mn_hi);
                S[nt][3] = __expf(S[nt][3] - mn_hi);
                s_lo += S[nt][0] + S[nt][1];
                s_hi += S[nt][2] + S[nt][3];
            }
            s_lo += __shfl_xor_sync(0xffffffffu, s_lo, 1);
            s_lo += __shfl_xor_sync(0xffffffffu, s_lo, 2);
            s_hi += __shfl_xor_sync(0xffffffffu, s_hi, 1);
            s_hi += __shfl_xor_sync(0xffffffffu, s_hi, 2);
            l_lo = l_lo * rs_lo + s_lo;
            l_hi = l_hi * rs_hi + s_hi;
#pragma unroll
            for (int dt = 0; dt < 4; dt++) {
                O[dt][0] *= rs_lo; O[dt][1] *= rs_lo;
                O[dt][2] *= rs_hi; O[dt][3] *= rs_hi;
            }

            // ---- PV ----
#pragma unroll
            for (int ks = 0; ks < 4; ks++) {
                const unsigned p0 = pack_h2(S[2 * ks][0], S[2 * ks][1]);
                const unsigned p1 = pack_h2(S[2 * ks][2], S[2 * ks][3]);
                const unsigned p2 = pack_h2(S[2 * ks + 1][0], S[2 * ks + 1][1]);
                const unsigned p3 = pack_h2(S[2 * ks + 1][2], S[2 * ks + 1][3]);
#pragma unroll
                for (int dt2 = 0; dt2 < 2; dt2++) {
                    const int rowd = dt2 * 16 + ((lane >> 4) << 3) + (lane & 7);
                    const int colk = kc * 64 + ks * 16 + ((lane >> 3) & 1) * 8;
                    unsigned v0, v1, v2, v3;
                    ldsm4(v0, v1, v2, v3, smem_u32(&Vts[rowd * 520 + colk]));
                    mma16816(O[dt2 * 2],     p0, p1, p2, p3, v0, v1);
                    mma16816(O[dt2 * 2 + 1], p0, p1, p2, p3, v2, v3);
                }
            }
        }

        // ---- write ----
        const float il_lo = 1.0f / l_lo, il_hi = 1.0f / l_hi;
#pragma unroll
        for (int dt = 0; dt < 4; dt++) {
            __half2 o_lo = __floats2half2_rn(O[dt][0] * il_lo, O[dt][1] * il_lo);
            __half2 o_hi = __floats2half2_rn(O[dt][2] * il_hi, O[dt][3] * il_hi);
            const size_t base = ((size_t)b * SEQ + rlo) * C_DIM + h * HD + dt * 8 + (lane & 3) * 2;
            *(__half2*)&g_attno[base] = o_lo;
            *(__half2*)&g_attno[base + (size_t)8 * C_DIM] = o_hi;
        }
    }
}

// ============================================================
// Launch
// ============================================================
extern "C" void kernel_launch(void* const* d_in, const int* in_sizes, int n_in,
                              void* d_out, int out_size)
{
    (void)in_sizes; (void)n_in; (void)out_size;
    const float* x1     = (const float*)d_in[0];
    const float* x2     = (const float*)d_in[1];
    const float* q_w    = (const float*)d_in[2];
    const float* q_b    = (const float*)d_in[3];
    const float* kv_w   = (const float*)d_in[4];
    const float* v_b    = (const float*)d_in[5];
    const float* ls     = (const float*)d_in[6];
    const float* proj_w = (const float*)d_in[7];
    const float* proj_b = (const float*)d_in[8];
    float* out = (float*)d_out;

    __half *x1h, *x2h, *x2l, *wqh, *wql, *wkvh, *wkvl, *wph, *wpl, *attno;
    cudaGetSymbolAddress((void**)&x1h,  g_x1h);
    cudaGetSymbolAddress((void**)&x2h,  g_x2h);  cudaGetSymbolAddress((void**)&x2l,  g_x2l);
    cudaGetSymbolAddress((void**)&wqh,  g_wqh);  cudaGetSymbolAddress((void**)&wql,  g_wql);
    cudaGetSymbolAddress((void**)&wkvh, g_wkvh); cudaGetSymbolAddress((void**)&wkvl, g_wkvl);
    cudaGetSymbolAddress((void**)&wph,  g_wph);  cudaGetSymbolAddress((void**)&wpl,  g_wpl);
    cudaGetSymbolAddress((void**)&attno, g_attno);

    const int nX8 = MROWS * C_DIM / 8;
    tohalf_kernel<<<(nX8 + 255) / 256, 256>>>(x1, x1h, nX8);
    split_kernel<<<(nX8 + 255) / 256, 256>>>(x2, x2h, x2l, nX8);
    split_kernel<<<(C_DIM * C_DIM / 8 + 255) / 256, 256>>>(q_w, wqh, wql, C_DIM * C_DIM / 8);
    split_kernel<<<(2 * C_DIM * C_DIM / 8 + 255) / 256, 256>>>(kv_w, wkvh, wkvl, 2 * C_DIM * C_DIM / 8);
    split_kernel<<<(C_DIM * C_DIM / 8 + 255) / 256, 256>>>(proj_w, wph, wpl, C_DIM * C_DIM / 8);

    // q projection (2-term) + fused normalize/scale -> g_qh
    gemm_kernel<C_DIM, 0><<<dim3(C_DIM / 64, MROWS / 128), 256>>>(x1h, nullptr, wqh, wql, q_b, ls, nullptr);
    // kv projection (3-term) + fused k-normalize -> g_kh; v -> g_vt
    gemm_kernel<2 * C_DIM, 1><<<dim3(2 * C_DIM / 64, MROWS / 128), 256>>>(x2h, x2l, wkvh, wkvl, v_b, nullptr, nullptr);

    const int smem_bytes = (512 * 32 + 32 * 520) * (int)sizeof(__half); // 66048
    cudaFuncSetAttribute(attn_kernel, cudaFuncAttributeMaxDynamicSharedMemorySize, smem_bytes);
    attn_kernel<<<BH, 256, smem_bytes>>>();

    // output projection (2-term)
    gemm_kernel<C_DIM, 2><<<dim3(C_DIM / 64, MROWS / 128), 256>>>(attno, nullptr, wph, wpl, proj_b, nullptr, out);
}

// round 6
// speedup vs baseline: 6.5497x; 1.2581x over previous
#include <cuda_runtime.h>
#include <cuda_fp16.h>

#define C_DIM 192
#define HEADS 6
#define HD 32
#define BATCH 128
#define SEQ 512
#define MROWS (BATCH * SEQ)        // 65536
#define BH (BATCH * HEADS)         // 768
#define LOGIT_MAX 4.6051701859880914f
#define LOG2E 1.4426950408889634f

// ---------------- device-global scratch ----------------
__device__ __half g_qh[(size_t)BH * SEQ * HD];    // normalized * scale * log2e q
__device__ __half g_kh[(size_t)BH * SEQ * HD];    // normalized k
__device__ __half g_vt[(size_t)BH * HD * SEQ];    // v transposed per (b,h): [d][n]
__device__ __half g_attno[(size_t)MROWS * C_DIM];
__device__ __half g_x1h[(size_t)MROWS * C_DIM];
__device__ __half g_x2h[(size_t)MROWS * C_DIM];
__device__ __half g_wqh[C_DIM * C_DIM];
__device__ __half g_wql[C_DIM * C_DIM];
__device__ __half g_wkvh[2 * C_DIM * C_DIM];
__device__ __half g_wkvl[2 * C_DIM * C_DIM];
__device__ __half g_wph[C_DIM * C_DIM];
__device__ __half g_wpl[C_DIM * C_DIM];

// ---------------- helpers ----------------
__device__ __forceinline__ unsigned smem_u32(const void* p) {
    return (unsigned)__cvta_generic_to_shared(p);
}
__device__ __forceinline__ void ldsm4(unsigned& r0, unsigned& r1, unsigned& r2, unsigned& r3, unsigned a) {
    asm volatile("ldmatrix.sync.aligned.m8n8.x4.shared.b16 {%0,%1,%2,%3},[%4];\n"
                 : "=r"(r0), "=r"(r1), "=r"(r2), "=r"(r3) : "r"(a));
}
__device__ __forceinline__ void mma16816(float* c, unsigned a0, unsigned a1, unsigned a2, unsigned a3,
                                         unsigned b0, unsigned b1) {
    asm volatile("mma.sync.aligned.m16n8k16.row.col.f32.f16.f16.f32 "
                 "{%0,%1,%2,%3},{%4,%5,%6,%7},{%8,%9},{%0,%1,%2,%3};\n"
                 : "+f"(c[0]), "+f"(c[1]), "+f"(c[2]), "+f"(c[3])
                 : "r"(a0), "r"(a1), "r"(a2), "r"(a3), "r"(b0), "r"(b1));
}
__device__ __forceinline__ void split2(float x, float y, __half2& hi, __half2& lo) {
    __half hx = __float2half_rn(x), hy = __float2half_rn(y);
    hi = __halves2half2(hx, hy);
    lo = __floats2half2_rn(x - __half2float(hx), y - __half2float(hy));
}
__device__ __forceinline__ unsigned pack_h2(float a, float b) {
    __half2 t = __floats2half2_rn(a, b);
    return *(unsigned*)&t;
}
__device__ __forceinline__ float ex2(float x) {
    float y;
    asm("ex2.approx.ftz.f32 %0, %1;" : "=f"(y) : "f"(x));
    return y;
}
__device__ __forceinline__ void cpa16(void* s, const void* g) {
    asm volatile("cp.async.ca.shared.global [%0], [%1], 16;\n" :: "r"(smem_u32(s)), "l"(g));
}
__device__ __forceinline__ void cpa_commit() { asm volatile("cp.async.commit_group;\n"); }
__device__ __forceinline__ void cpa_wait1()  { asm volatile("cp.async.wait_group 1;\n"); }
__device__ __forceinline__ void cpa_wait0()  { asm volatile("cp.async.wait_group 0;\n"); }

// ============================================================
// fp32 -> (hi, lo) fp16 split (weights). 8 elems per thread.
// ============================================================
__global__ __launch_bounds__(256)
void split_kernel(const float* __restrict__ src, __half* __restrict__ hi,
                  __half* __restrict__ lo, int n8)
{
    const int i = blockIdx.x * 256 + threadIdx.x;
    if (i >= n8) return;
    const float4 a = *(const float4*)&src[(size_t)i * 8];
    const float4 b = *(const float4*)&src[(size_t)i * 8 + 4];
    __half2 h[4], l[4];
    split2(a.x, a.y, h[0], l[0]);
    split2(a.z, a.w, h[1], l[1]);
    split2(b.x, b.y, h[2], l[2]);
    split2(b.z, b.w, h[3], l[3]);
    *(uint4*)&hi[(size_t)i * 8] = *(uint4*)h;
    *(uint4*)&lo[(size_t)i * 8] = *(uint4*)l;
}

// fp32 -> fp16. 8 elems per thread.
__global__ __launch_bounds__(256)
void tohalf_kernel(const float* __restrict__ src, __half* __restrict__ hi, int n8)
{
    const int i = blockIdx.x * 256 + threadIdx.x;
    if (i >= n8) return;
    const float4 a = *(const float4*)&src[(size_t)i * 8];
    const float4 b = *(const float4*)&src[(size_t)i * 8 + 4];
    __half2 h[4];
    h[0] = __floats2half2_rn(a.x, a.y);
    h[1] = __floats2half2_rn(a.z, a.w);
    h[2] = __floats2half2_rn(b.x, b.y);
    h[3] = __floats2half2_rn(b.z, b.w);
    *(uint4*)&hi[(size_t)i * 8] = *(uint4*)h;
}

// ============================================================
// Tensor-core GEMM: A fp16 single, W split (hi+lo), 2-term.
// cp.async double buffer. BM=128, BN=64, BK=32, 256 thr, 8 warps.
// MODE 0: epilogue +q_b, L2-norm, *exp(ls)*log2e -> g_qh fp16
// MODE 1: k cols: L2-norm -> g_kh; v cols: +v_b -> g_vt^T fp16
// MODE 2: -> d_out fp32 (+bias)
// ============================================================
template<int NC, int MODE>
__global__ __launch_bounds__(256)
void gemm_kernel(const __half* __restrict__ Ah_g,
                 const __half* __restrict__ Wh_g, const __half* __restrict__ Wl_g,
                 const float* __restrict__ bias, const float* __restrict__ ls,
                 float* __restrict__ outf)
{
    __shared__ __half Ah[2][128][40];
    __shared__ __half Bh[2][64][40];
    __shared__ __half Bl[2][64][40];

    const int tid = threadIdx.x, w = tid >> 5, lane = tid & 31;
    const int wm = w >> 1, wn = w & 1;
    const int row0 = blockIdx.y * 128, col0 = blockIdx.x * 64;

    auto load_stage = [&](int s, int buf) {
        const int k0 = s * 32;
#pragma unroll
        for (int j = 0; j < 2; j++) {
            const int idx = j * 256 + tid;
            const int r = idx >> 2, c8 = (idx & 3) * 8;
            cpa16(&Ah[buf][r][c8], &Ah_g[(size_t)(row0 + r) * C_DIM + k0 + c8]);
        }
        {
            const int r = tid >> 2, c8 = (tid & 3) * 8;
            cpa16(&Bh[buf][r][c8], &Wh_g[(size_t)(col0 + r) * C_DIM + k0 + c8]);
            cpa16(&Bl[buf][r][c8], &Wl_g[(size_t)(col0 + r) * C_DIM + k0 + c8]);
        }
    };

    float acc[2][4][4] = {};

    load_stage(0, 0);
    cpa_commit();

    for (int s = 0; s < 6; s++) {
        const int buf = s & 1;
        if (s < 5) { load_stage(s + 1, buf ^ 1); cpa_commit(); cpa_wait1(); }
        else       { cpa_wait0(); }
        __syncthreads();

#pragma unroll
        for (int kf = 0; kf < 2; kf++) {
            unsigned ah[2][4];
#pragma unroll
            for (int mf = 0; mf < 2; mf++) {
                unsigned a = smem_u32(&Ah[buf][wm * 32 + mf * 16 + (lane & 15)][kf * 16 + (lane >> 4) * 8]);
                ldsm4(ah[mf][0], ah[mf][1], ah[mf][2], ah[mf][3], a);
            }
            unsigned bh_[4][2], bl_[4][2];
#pragma unroll
            for (int nt2 = 0; nt2 < 2; nt2++) {
                const int rowb = wn * 32 + nt2 * 16 + ((lane >> 4) << 3) + (lane & 7);
                const int colb = kf * 16 + ((lane >> 3) & 1) * 8;
                unsigned r0, r1, r2, r3;
                ldsm4(r0, r1, r2, r3, smem_u32(&Bh[buf][rowb][colb]));
                bh_[nt2 * 2][0] = r0; bh_[nt2 * 2][1] = r1;
                bh_[nt2 * 2 + 1][0] = r2; bh_[nt2 * 2 + 1][1] = r3;
                ldsm4(r0, r1, r2, r3, smem_u32(&Bl[buf][rowb][colb]));
                bl_[nt2 * 2][0] = r0; bl_[nt2 * 2][1] = r1;
                bl_[nt2 * 2 + 1][0] = r2; bl_[nt2 * 2 + 1][1] = r3;
            }
#pragma unroll
            for (int mf = 0; mf < 2; mf++)
#pragma unroll
                for (int nt = 0; nt < 4; nt++) {
                    mma16816(acc[mf][nt], ah[mf][0], ah[mf][1], ah[mf][2], ah[mf][3], bh_[nt][0], bh_[nt][1]);
                    mma16816(acc[mf][nt], ah[mf][0], ah[mf][1], ah[mf][2], ah[mf][3], bl_[nt][0], bl_[nt][1]);
                }
        }
        __syncthreads();
    }

    // ---- epilogue ----
    if (MODE == 2) {
#pragma unroll
        for (int mf = 0; mf < 2; mf++) {
            const int rlo = row0 + wm * 32 + mf * 16 + (lane >> 2);
#pragma unroll
            for (int nt = 0; nt < 4; nt++) {
                const int cc = col0 + wn * 32 + nt * 8 + (lane & 3) * 2;
#pragma unroll
                for (int half_ = 0; half_ < 2; half_++) {
                    const int r = rlo + half_ * 8;
                    float2 o = make_float2(acc[mf][nt][half_ * 2 + 0] + bias[cc],
                                           acc[mf][nt][half_ * 2 + 1] + bias[cc + 1]);
                    *(float2*)&outf[(size_t)r * C_DIM + cc] = o;
                }
            }
        }
        return;
    }

    const int cbase = col0 + wn * 32;           // 32-aligned
    const bool is_v = (MODE == 1) && (cbase >= C_DIM);

    if (is_v) {
#pragma unroll
        for (int mf = 0; mf < 2; mf++) {
            const int rlo = row0 + wm * 32 + mf * 16 + (lane >> 2);
#pragma unroll
            for (int nt = 0; nt < 4; nt++) {
                const int cv = cbase - C_DIM + nt * 8 + (lane & 3) * 2;
                const int h = cv >> 5, d = cv & 31;
#pragma unroll
                for (int half_ = 0; half_ < 2; half_++) {
                    const int r = rlo + half_ * 8;
                    const int b = r >> 9, n = r & 511;
                    const float v0 = acc[mf][nt][half_ * 2 + 0] + bias[cv];
                    const float v1 = acc[mf][nt][half_ * 2 + 1] + bias[cv + 1];
                    g_vt[((size_t)(b * HEADS + h) * HD + d) * SEQ + n]     = __float2half_rn(v0);
                    g_vt[((size_t)(b * HEADS + h) * HD + d + 1) * SEQ + n] = __float2half_rn(v1);
                }
            }
        }
        return;
    }

    // q or k columns: fused L2-normalize (+ scale*log2e for q)
    const int h = cbase >> 5;
    float hsc = 1.0f;
    if (MODE == 0) hsc = __expf(fminf(ls[h], LOGIT_MAX)) * LOG2E;

#pragma unroll
    for (int mf = 0; mf < 2; mf++) {
        const int rlo = row0 + wm * 32 + mf * 16 + (lane >> 2);
        float va[4][4];
        float ss0 = 0.f, ss1 = 0.f;
#pragma unroll
        for (int nt = 0; nt < 4; nt++) {
            const int cc = cbase + nt * 8 + (lane & 3) * 2;
            float b0 = 0.f, b1 = 0.f;
            if (MODE == 0) { b0 = bias[cc]; b1 = bias[cc + 1]; }
            va[nt][0] = acc[mf][nt][0] + b0;
            va[nt][1] = acc[mf][nt][1] + b1;
            va[nt][2] = acc[mf][nt][2] + b0;
            va[nt][3] = acc[mf][nt][3] + b1;
            ss0 += va[nt][0] * va[nt][0] + va[nt][1] * va[nt][1];
            ss1 += va[nt][2] * va[nt][2] + va[nt][3] * va[nt][3];
        }
        ss0 += __shfl_xor_sync(0xffffffffu, ss0, 1);
        ss0 += __shfl_xor_sync(0xffffffffu, ss0, 2);
        ss1 += __shfl_xor_sync(0xffffffffu, ss1, 1);
        ss1 += __shfl_xor_sync(0xffffffffu, ss1, 2);
        const float inv0 = hsc / fmaxf(sqrtf(ss0), 1e-12f);
        const float inv1 = hsc / fmaxf(sqrtf(ss1), 1e-12f);

#pragma unroll
        for (int half_ = 0; half_ < 2; half_++) {
            const int r = rlo + half_ * 8;
            const int b = r >> 9, n = r & 511;
            const float inv = half_ ? inv1 : inv0;
            const size_t base = (((size_t)(b * HEADS + h) << 9) | n) * HD;
#pragma unroll
            for (int nt = 0; nt < 4; nt++) {
                const int d = nt * 8 + (lane & 3) * 2;
                const float v0 = va[nt][half_ * 2 + 0] * inv;
                const float v1 = va[nt][half_ * 2 + 1] * inv;
                __half* dst = (MODE == 0) ? g_qh : g_kh;
                *(__half2*)&dst[base + d] = __floats2half2_rn(v0, v1);
            }
        }
    }
}

// ============================================================
// Attention per (b,h). 256 thr, 8 warps, 3 CTA/SM.
// Fixed-max softmax in exp2 domain: logits bounded by scale
// (cosine attention), so P = ex2(s2 - scale*log2e) needs no
// running max and no O rescaling.
// ============================================================
__device__ __forceinline__ unsigned kswz(int r, int cbytes) {
    return r * 64 + (cbytes ^ ((r & 6) * 8));
}

__global__ __launch_bounds__(256, 3)
void attn_kernel(const float* __restrict__ ls)
{
    extern __shared__ __half sm[];
    __half* Khs = sm;                    // 512 rows x 64B, swizzled
    __half* Vts = sm + 512 * 32;         // [32][520]

    const int bh = blockIdx.x;
    const int b = bh / HEADS, h = bh % HEADS;
    const int tid = threadIdx.x, w = tid >> 5, lane = tid & 31;

    const float bias2 = __expf(fminf(ls[h], LOGIT_MAX)) * LOG2E;  // upper bound of s2

    const __half* kh = g_kh + (size_t)bh * SEQ * HD;
    const __half* vt = g_vt + (size_t)bh * HD * SEQ;

#pragma unroll
    for (int p = 0; p < 8; p++) {
        const int idx = p * 256 + tid;
        const int r = idx >> 2, cb = (idx & 3) * 16;
        *(uint4*)((char*)Khs + kswz(r, cb)) = *(const uint4*)&kh[r * HD + cb / 2];
    }
#pragma unroll
    for (int p = 0; p < 8; p++) {
        const int idx = p * 256 + tid;
        const int d = idx >> 6, c8 = (idx & 63) * 8;
        *(uint4*)&Vts[d * 520 + c8] = *(const uint4*)&vt[d * SEQ + c8];
    }
    __syncthreads();

    const __half* qh = g_qh + (size_t)bh * SEQ * HD;

    for (int mf = 0; mf < 4; mf++) {
        const int m0 = w * 64 + mf * 16;
        const int rlo = m0 + (lane >> 2);

        unsigned qhf[2][4];
#pragma unroll
        for (int kf = 0; kf < 2; kf++) {
            const int kb = kf * 16 + (lane & 3) * 2;
            qhf[kf][0] = *(const unsigned*)&qh[(size_t)rlo * HD + kb];
            qhf[kf][1] = *(const unsigned*)&qh[(size_t)(rlo + 8) * HD + kb];
            qhf[kf][2] = *(const unsigned*)&qh[(size_t)rlo * HD + kb + 8];
            qhf[kf][3] = *(const unsigned*)&qh[(size_t)(rlo + 8) * HD + kb + 8];
        }

        float O[4][4] = {};
        float l_lo = 0.f, l_hi = 0.f;

        for (int kc = 0; kc < 8; kc++) {
            float S[8][4] = {};
#pragma unroll
            for (int nt2 = 0; nt2 < 4; nt2++) {
                const int rowb = kc * 64 + nt2 * 16 + ((lane >> 4) << 3) + (lane & 7);
                const int colb2 = ((lane >> 3) & 1) * 16;   // bytes
#pragma unroll
                for (int kf = 0; kf < 2; kf++) {
                    const unsigned off = kswz(rowb, kf * 32 + colb2);
                    unsigned kh0, kh1, kh2, kh3;
                    ldsm4(kh0, kh1, kh2, kh3, smem_u32((char*)Khs + off));
                    mma16816(S[nt2 * 2],     qhf[kf][0], qhf[kf][1], qhf[kf][2], qhf[kf][3], kh0, kh1);
                    mma16816(S[nt2 * 2 + 1], qhf[kf][0], qhf[kf][1], qhf[kf][2], qhf[kf][3], kh2, kh3);
                }
            }

            // ---- fixed-max softmax numerator ----
#pragma unroll
            for (int nt = 0; nt < 8; nt++) {
                S[nt][0] = ex2(S[nt][0] - bias2);
                S[nt][1] = ex2(S[nt][1] - bias2);
                S[nt][2] = ex2(S[nt][2] - bias2);
                S[nt][3] = ex2(S[nt][3] - bias2);
                l_lo += S[nt][0] + S[nt][1];
                l_hi += S[nt][2] + S[nt][3];
            }

            // ---- PV ----
#pragma unroll
            for (int ks = 0; ks < 4; ks++) {
                const unsigned p0 = pack_h2(S[2 * ks][0], S[2 * ks][1]);
                const unsigned p1 = pack_h2(S[2 * ks][2], S[2 * ks][3]);
                const unsigned p2 = pack_h2(S[2 * ks + 1][0], S[2 * ks + 1][1]);
                const unsigned p3 = pack_h2(S[2 * ks + 1][2], S[2 * ks + 1][3]);
#pragma unroll
                for (int dt2 = 0; dt2 < 2; dt2++) {
                    const int rowd = dt2 * 16 + ((lane >> 4) << 3) + (lane & 7);
                    const int colk = kc * 64 + ks * 16 + ((lane >> 3) & 1) * 8;
                    unsigned v0, v1, v2, v3;
                    ldsm4(v0, v1, v2, v3, smem_u32(&Vts[rowd * 520 + colk]));
                    mma16816(O[dt2 * 2],     p0, p1, p2, p3, v0, v1);
                    mma16816(O[dt2 * 2 + 1], p0, p1, p2, p3, v2, v3);
                }
            }
        }

        // ---- final l reduction + write ----
        l_lo += __shfl_xor_sync(0xffffffffu, l_lo, 1);
        l_lo += __shfl_xor_sync(0xffffffffu, l_lo, 2);
        l_hi += __shfl_xor_sync(0xffffffffu, l_hi, 1);
        l_hi += __shfl_xor_sync(0xffffffffu, l_hi, 2);
        const float il_lo = 1.0f / l_lo, il_hi = 1.0f / l_hi;
#pragma unroll
        for (int dt = 0; dt < 4; dt++) {
            __half2 o_lo = __floats2half2_rn(O[dt][0] * il_lo, O[dt][1] * il_lo);
            __half2 o_hi = __floats2half2_rn(O[dt][2] * il_hi, O[dt][3] * il_hi);
            const size_t base = ((size_t)b * SEQ + rlo) * C_DIM + h * HD + dt * 8 + (lane & 3) * 2;
            *(__half2*)&g_attno[base] = o_lo;
            *(__half2*)&g_attno[base + (size_t)8 * C_DIM] = o_hi;
        }
    }
}

// ============================================================
// Launch
// ============================================================
extern "C" void kernel_launch(void* const* d_in, const int* in_sizes, int n_in,
                              void* d_out, int out_size)
{
    (void)in_sizes; (void)n_in; (void)out_size;
    const float* x1     = (const float*)d_in[0];
    const float* x2     = (const float*)d_in[1];
    const float* q_w    = (const float*)d_in[2];
    const float* q_b    = (const float*)d_in[3];
    const float* kv_w   = (const float*)d_in[4];
    const float* v_b    = (const float*)d_in[5];
    const float* ls     = (const float*)d_in[6];
    const float* proj_w = (const float*)d_in[7];
    const float* proj_b = (const float*)d_in[8];
    float* out = (float*)d_out;

    __half *x1h, *x2h, *wqh, *wql, *wkvh, *wkvl, *wph, *wpl, *attno;
    cudaGetSymbolAddress((void**)&x1h,  g_x1h);
    cudaGetSymbolAddress((void**)&x2h,  g_x2h);
    cudaGetSymbolAddress((void**)&wqh,  g_wqh);  cudaGetSymbolAddress((void**)&wql,  g_wql);
    cudaGetSymbolAddress((void**)&wkvh, g_wkvh); cudaGetSymbolAddress((void**)&wkvl, g_wkvl);
    cudaGetSymbolAddress((void**)&wph,  g_wph);  cudaGetSymbolAddress((void**)&wpl,  g_wpl);
    cudaGetSymbolAddress((void**)&attno, g_attno);

    const int nX8 = MROWS * C_DIM / 8;
    tohalf_kernel<<<(nX8 + 255) / 256, 256>>>(x1, x1h, nX8);
    tohalf_kernel<<<(nX8 + 255) / 256, 256>>>(x2, x2h, nX8);
    split_kernel<<<(C_DIM * C_DIM / 8 + 255) / 256, 256>>>(q_w, wqh, wql, C_DIM * C_DIM / 8);
    split_kernel<<<(2 * C_DIM * C_DIM / 8 + 255) / 256, 256>>>(kv_w, wkvh, wkvl, 2 * C_DIM * C_DIM / 8);
    split_kernel<<<(C_DIM * C_DIM / 8 + 255) / 256, 256>>>(proj_w, wph, wpl, C_DIM * C_DIM / 8);

    // q projection + fused normalize/scale(log2e) -> g_qh
    gemm_kernel<C_DIM, 0><<<dim3(C_DIM / 64, MROWS / 128), 256>>>(x1h, wqh, wql, q_b, ls, nullptr);
    // kv projection + fused k-normalize -> g_kh; v -> g_vt
    gemm_kernel<2 * C_DIM, 1><<<dim3(2 * C_DIM / 64, MROWS / 128), 256>>>(x2h, wkvh, wkvl, v_b, nullptr, nullptr);

    const int smem_bytes = (512 * 32 + 32 * 520) * (int)sizeof(__half); // 66048
    cudaFuncSetAttribute(attn_kernel, cudaFuncAttributeMaxDynamicSharedMemorySize, smem_bytes);
    attn_kernel<<<BH, 256, smem_bytes>>>(ls);

    // output projection
    gemm_kernel<C_DIM, 2><<<dim3(C_DIM / 64, MROWS / 128), 256>>>(attno, wph, wpl, proj_b, nullptr, out);
}

// round 9
// speedup vs baseline: 6.7186x; 1.0258x over previous
#include <cuda_runtime.h>
#include <cuda_fp16.h>

#define C_DIM 192
#define HEADS 6
#define HD 32
#define BATCH 128
#define SEQ 512
#define MROWS (BATCH * SEQ)        // 65536
#define BH (BATCH * HEADS)         // 768
#define LOGIT_MAX 4.6051701859880914f
#define LOG2E 1.4426950408889634f

// ---------------- device-global scratch ----------------
__device__ __half g_qh[(size_t)BH * SEQ * HD];    // normalized * scale * log2e q
__device__ __half g_kh[(size_t)BH * SEQ * HD];    // normalized k
__device__ __half g_vt[(size_t)BH * HD * SEQ];    // v transposed per (b,h): [d][n]
__device__ __half g_attno[(size_t)MROWS * C_DIM];
__device__ __half g_x1h[(size_t)MROWS * C_DIM];
__device__ __half g_x2h[(size_t)MROWS * C_DIM];
__device__ __half g_wqh[C_DIM * C_DIM];
__device__ __half g_wql[C_DIM * C_DIM];
__device__ __half g_wkvh[2 * C_DIM * C_DIM];
__device__ __half g_wkvl[2 * C_DIM * C_DIM];
__device__ __half g_wph[C_DIM * C_DIM];
__device__ __half g_wpl[C_DIM * C_DIM];

// ---------------- helpers ----------------
__device__ __forceinline__ unsigned smem_u32(const void* p) {
    return (unsigned)__cvta_generic_to_shared(p);
}
__device__ __forceinline__ void ldsm4(unsigned& r0, unsigned& r1, unsigned& r2, unsigned& r3, unsigned a) {
    asm volatile("ldmatrix.sync.aligned.m8n8.x4.shared.b16 {%0,%1,%2,%3},[%4];\n"
                 : "=r"(r0), "=r"(r1), "=r"(r2), "=r"(r3) : "r"(a));
}
__device__ __forceinline__ void mma16816(float* c, unsigned a0, unsigned a1, unsigned a2, unsigned a3,
                                         unsigned b0, unsigned b1) {
    asm volatile("mma.sync.aligned.m16n8k16.row.col.f32.f16.f16.f32 "
                 "{%0,%1,%2,%3},{%4,%5,%6,%7},{%8,%9},{%0,%1,%2,%3};\n"
                 : "+f"(c[0]), "+f"(c[1]), "+f"(c[2]), "+f"(c[3])
                 : "r"(a0), "r"(a1), "r"(a2), "r"(a3), "r"(b0), "r"(b1));
}
__device__ __forceinline__ void split2(float x, float y, __half2& hi, __half2& lo) {
    __half hx = __float2half_rn(x), hy = __float2half_rn(y);
    hi = __halves2half2(hx, hy);
    lo = __floats2half2_rn(x - __half2float(hx), y - __half2float(hy));
}
__device__ __forceinline__ unsigned pack_h2(float a, float b) {
    __half2 t = __floats2half2_rn(a, b);
    return *(unsigned*)&t;
}
__device__ __forceinline__ float ex2(float x) {
    float y;
    asm("ex2.approx.ftz.f32 %0, %1;" : "=f"(y) : "f"(x));
    return y;
}
__device__ __forceinline__ void cpa16(void* s, const void* g) {
    asm volatile("cp.async.ca.shared.global [%0], [%1], 16;\n" :: "r"(smem_u32(s)), "l"(g));
}
__device__ __forceinline__ void cpa_commit() { asm volatile("cp.async.commit_group;\n"); }
__device__ __forceinline__ void cpa_wait1()  { asm volatile("cp.async.wait_group 1;\n"); }
__device__ __forceinline__ void cpa_wait0()  { asm volatile("cp.async.wait_group 0;\n"); }

// ============================================================
// Combined x1+x2 fp32 -> fp16. 6144 blocks per tensor (grid 12288).
// Each thread converts 8 elems; per-tensor items = MROWS*C_DIM/8 = 1,572,864.
// ============================================================
__global__ __launch_bounds__(256)
void tohalf2_kernel(const float* __restrict__ x1, const float* __restrict__ x2)
{
    int blk = blockIdx.x;
    const float* src;  __half* dst;
    if (blk < 6144) { src = x1; dst = g_x1h; }
    else            { src = x2; dst = g_x2h; blk -= 6144; }
    const int i = blk * 256 + threadIdx.x;     // < 1,572,864
    const float4 a = *(const float4*)&src[(size_t)i * 8];
    const float4 b = *(const float4*)&src[(size_t)i * 8 + 4];
    __half2 h[4];
    h[0] = __floats2half2_rn(a.x, a.y);
    h[1] = __floats2half2_rn(a.z, a.w);
    h[2] = __floats2half2_rn(b.x, b.y);
    h[3] = __floats2half2_rn(b.z, b.w);
    *(uint4*)&dst[(size_t)i * 8] = *(uint4*)h;
}

// ============================================================
// Combined weight split (q_w, kv_w, proj_w) -> hi/lo fp16.
// blocks: [0,18) q_w, [18,54) kv_w, [54,72) proj_w.
// (192*192/8 = 4608 items = 18 blocks; kv 2x -> 36 blocks.)
// ============================================================
__global__ __launch_bounds__(256)
void split3_kernel(const float* __restrict__ qw, const float* __restrict__ kvw,
                   const float* __restrict__ pw)
{
    int blk = blockIdx.x;
    const float* src;  __half *hi, *lo;
    if (blk < 18)      { src = qw;  hi = g_wqh;  lo = g_wql;  }
    else if (blk < 54) { src = kvw; hi = g_wkvh; lo = g_wkvl; blk -= 18; }
    else               { src = pw;  hi = g_wph;  lo = g_wpl;  blk -= 54; }
    const int i = blk * 256 + threadIdx.x;
    const float4 a = *(const float4*)&src[(size_t)i * 8];
    const float4 b = *(const float4*)&src[(size_t)i * 8 + 4];
    __half2 h[4], l[4];
    split2(a.x, a.y, h[0], l[0]);
    split2(a.z, a.w, h[1], l[1]);
    split2(b.x, b.y, h[2], l[2]);
    split2(b.z, b.w, h[3], l[3]);
    *(uint4*)&hi[(size_t)i * 8] = *(uint4*)h;
    *(uint4*)&lo[(size_t)i * 8] = *(uint4*)l;
}

// ============================================================
// Tensor-core GEMM: A fp16 single, W split (hi+lo), 2-term.
// cp.async double buffer. BM=128, BN=64, BK=32, 256 thr, 8 warps.
// MODE 0: epilogue +q_b, L2-norm, *exp(ls)*log2e -> g_qh fp16
// MODE 1: k cols: L2-norm -> g_kh; v cols: +v_b -> g_vt^T fp16
// MODE 2: -> d_out fp32 (+bias)
// ============================================================
template<int NC, int MODE>
__global__ __launch_bounds__(256)
void gemm_kernel(const __half* __restrict__ Ah_g,
                 const __half* __restrict__ Wh_g, const __half* __restrict__ Wl_g,
                 const float* __restrict__ bias, const float* __restrict__ ls,
                 float* __restrict__ outf)
{
    __shared__ __half Ah[2][128][40];
    __shared__ __half Bh[2][64][40];
    __shared__ __half Bl[2][64][40];

    const int tid = threadIdx.x, w = tid >> 5, lane = tid & 31;
    const int wm = w >> 1, wn = w & 1;
    const int row0 = blockIdx.y * 128, col0 = blockIdx.x * 64;

    auto load_stage = [&](int s, int buf) {
        const int k0 = s * 32;
#pragma unroll
        for (int j = 0; j < 2; j++) {
            const int idx = j * 256 + tid;
            const int r = idx >> 2, c8 = (idx & 3) * 8;
            cpa16(&Ah[buf][r][c8], &Ah_g[(size_t)(row0 + r) * C_DIM + k0 + c8]);
        }
        {
            const int r = tid >> 2, c8 = (tid & 3) * 8;
            cpa16(&Bh[buf][r][c8], &Wh_g[(size_t)(col0 + r) * C_DIM + k0 + c8]);
            cpa16(&Bl[buf][r][c8], &Wl_g[(size_t)(col0 + r) * C_DIM + k0 + c8]);
        }
    };

    float acc[2][4][4] = {};

    load_stage(0, 0);
    cpa_commit();

    for (int s = 0; s < 6; s++) {
        const int buf = s & 1;
        if (s < 5) { load_stage(s + 1, buf ^ 1); cpa_commit(); cpa_wait1(); }
        else       { cpa_wait0(); }
        __syncthreads();

#pragma unroll
        for (int kf = 0; kf < 2; kf++) {
            unsigned ah[2][4];
#pragma unroll
            for (int mf = 0; mf < 2; mf++) {
                unsigned a = smem_u32(&Ah[buf][wm * 32 + mf * 16 + (lane & 15)][kf * 16 + (lane >> 4) * 8]);
                ldsm4(ah[mf][0], ah[mf][1], ah[mf][2], ah[mf][3], a);
            }
            unsigned bh_[4][2], bl_[4][2];
#pragma unroll
            for (int nt2 = 0; nt2 < 2; nt2++) {
                const int rowb = wn * 32 + nt2 * 16 + ((lane >> 4) << 3) + (lane & 7);
                const int colb = kf * 16 + ((lane >> 3) & 1) * 8;
                unsigned r0, r1, r2, r3;
                ldsm4(r0, r1, r2, r3, smem_u32(&Bh[buf][rowb][colb]));
                bh_[nt2 * 2][0] = r0; bh_[nt2 * 2][1] = r1;
                bh_[nt2 * 2 + 1][0] = r2; bh_[nt2 * 2 + 1][1] = r3;
                ldsm4(r0, r1, r2, r3, smem_u32(&Bl[buf][rowb][colb]));
                bl_[nt2 * 2][0] = r0; bl_[nt2 * 2][1] = r1;
                bl_[nt2 * 2 + 1][0] = r2; bl_[nt2 * 2 + 1][1] = r3;
            }
#pragma unroll
            for (int mf = 0; mf < 2; mf++)
#pragma unroll
                for (int nt = 0; nt < 4; nt++) {
                    mma16816(acc[mf][nt], ah[mf][0], ah[mf][1], ah[mf][2], ah[mf][3], bh_[nt][0], bh_[nt][1]);
                    mma16816(acc[mf][nt], ah[mf][0], ah[mf][1], ah[mf][2], ah[mf][3], bl_[nt][0], bl_[nt][1]);
                }
        }
        __syncthreads();
    }

    // ---- epilogue ----
    if (MODE == 2) {
#pragma unroll
        for (int mf = 0; mf < 2; mf++) {
            const int rlo = row0 + wm * 32 + mf * 16 + (lane >> 2);
#pragma unroll
            for (int nt = 0; nt < 4; nt++) {
                const int cc = col0 + wn * 32 + nt * 8 + (lane & 3) * 2;
#pragma unroll
                for (int half_ = 0; half_ < 2; half_++) {
                    const int r = rlo + half_ * 8;
                    float2 o = make_float2(acc[mf][nt][half_ * 2 + 0] + bias[cc],
                                           acc[mf][nt][half_ * 2 + 1] + bias[cc + 1]);
                    *(float2*)&outf[(size_t)r * C_DIM + cc] = o;
                }
            }
        }
        return;
    }

    const int cbase = col0 + wn * 32;           // 32-aligned
    const bool is_v = (MODE == 1) && (cbase >= C_DIM);

    if (is_v) {
        // v columns: add v_b, write transposed [d][n] fp16 (R6-proven path)
#pragma unroll
        for (int mf = 0; mf < 2; mf++) {
            const int rlo = row0 + wm * 32 + mf * 16 + (lane >> 2);
#pragma unroll
            for (int nt = 0; nt < 4; nt++) {
                const int cv = cbase - C_DIM + nt * 8 + (lane & 3) * 2;
                const int h = cv >> 5, d = cv & 31;
#pragma unroll
                for (int half_ = 0; half_ < 2; half_++) {
                    const int r = rlo + half_ * 8;
                    const int b = r >> 9, n = r & 511;
                    const float v0 = acc[mf][nt][half_ * 2 + 0] + bias[cv];
                    const float v1 = acc[mf][nt][half_ * 2 + 1] + bias[cv + 1];
                    g_vt[((size_t)(b * HEADS + h) * HD + d) * SEQ + n]     = __float2half_rn(v0);
                    g_vt[((size_t)(b * HEADS + h) * HD + d + 1) * SEQ + n] = __float2half_rn(v1);
                }
            }
        }
        return;
    }

    // q or k columns: fused L2-normalize (+ scale*log2e for q)
    const int h = cbase >> 5;
    float hsc = 1.0f;
    if (MODE == 0) hsc = __expf(fminf(ls[h], LOGIT_MAX)) * LOG2E;

#pragma unroll
    for (int mf = 0; mf < 2; mf++) {
        const int rlo = row0 + wm * 32 + mf * 16 + (lane >> 2);
        float va[4][4];
        float ss0 = 0.f, ss1 = 0.f;
#pragma unroll
        for (int nt = 0; nt < 4; nt++) {
            const int cc = cbase + nt * 8 + (lane & 3) * 2;
            float b0 = 0.f, b1 = 0.f;
            if (MODE == 0) { b0 = bias[cc]; b1 = bias[cc + 1]; }
            va[nt][0] = acc[mf][nt][0] + b0;
            va[nt][1] = acc[mf][nt][1] + b1;
            va[nt][2] = acc[mf][nt][2] + b0;
            va[nt][3] = acc[mf][nt][3] + b1;
            ss0 += va[nt][0] * va[nt][0] + va[nt][1] * va[nt][1];
            ss1 += va[nt][2] * va[nt][2] + va[nt][3] * va[nt][3];
        }
        ss0 += __shfl_xor_sync(0xffffffffu, ss0, 1);
        ss0 += __shfl_xor_sync(0xffffffffu, ss0, 2);
        ss1 += __shfl_xor_sync(0xffffffffu, ss1, 1);
        ss1 += __shfl_xor_sync(0xffffffffu, ss1, 2);
        const float inv0 = hsc / fmaxf(sqrtf(ss0), 1e-12f);
        const float inv1 = hsc / fmaxf(sqrtf(ss1), 1e-12f);

#pragma unroll
        for (int half_ = 0; half_ < 2; half_++) {
            const int r = rlo + half_ * 8;
            const int b = r >> 9, n = r & 511;
            const float inv = half_ ? inv1 : inv0;
            const size_t base = (((size_t)(b * HEADS + h) << 9) | n) * HD;
#pragma unroll
            for (int nt = 0; nt < 4; nt++) {
                const int d = nt * 8 + (lane & 3) * 2;
                const float v0 = va[nt][half_ * 2 + 0] * inv;
                const float v1 = va[nt][half_ * 2 + 1] * inv;
                __half* dst = (MODE == 0) ? g_qh : g_kh;
                *(__half2*)&dst[base + d] = __floats2half2_rn(v0, v1);
            }
        }
    }
}

// ============================================================
// Attention per (b,h). 256 thr, 8 warps, 3 CTA/SM.
// K in swizzled 64B-row smem; V^T [32][520] padded (R6-proven).
// Fixed-max exp2 softmax (cosine logits bounded by scale).
// ============================================================
__device__ __forceinline__ unsigned kswz(int r, int cbytes) {
    return r * 64 + (cbytes ^ ((r & 6) * 8));
}

__global__ __launch_bounds__(256, 3)
void attn_kernel(const float* __restrict__ ls)
{
    extern __shared__ __half sm[];
    __half* Khs = sm;                    // 512 rows x 64B, swizzled
    __half* Vts = sm + 512 * 32;         // [32][520]

    const int bh = blockIdx.x;
    const int b = bh / HEADS, h = bh % HEADS;
    const int tid = threadIdx.x, w = tid >> 5, lane = tid & 31;

    const float bias2 = __expf(fminf(ls[h], LOGIT_MAX)) * LOG2E;

    const __half* kh = g_kh + (size_t)bh * SEQ * HD;
    const __half* vt = g_vt + (size_t)bh * HD * SEQ;

#pragma unroll
    for (int p = 0; p < 8; p++) {
        const int idx = p * 256 + tid;
        const int r = idx >> 2, cb = (idx & 3) * 16;
        *(uint4*)((char*)Khs + kswz(r, cb)) = *(const uint4*)&kh[r * HD + cb / 2];
    }
#pragma unroll
    for (int p = 0; p < 8; p++) {
        const int idx = p * 256 + tid;
        const int d = idx >> 6, c8 = (idx & 63) * 8;
        *(uint4*)&Vts[d * 520 + c8] = *(const uint4*)&vt[d * SEQ + c8];
    }
    __syncthreads();

    const __half* qh = g_qh + (size_t)bh * SEQ * HD;

    for (int mf = 0; mf < 4; mf++) {
        const int m0 = w * 64 + mf * 16;
        const int rlo = m0 + (lane >> 2);

        unsigned qhf[2][4];
#pragma unroll
        for (int kf = 0; kf < 2; kf++) {
            const int kb = kf * 16 + (lane & 3) * 2;
            qhf[kf][0] = *(const unsigned*)&qh[(size_t)rlo * HD + kb];
            qhf[kf][1] = *(const unsigned*)&qh[(size_t)(rlo + 8) * HD + kb];
            qhf[kf][2] = *(const unsigned*)&qh[(size_t)rlo * HD + kb + 8];
            qhf[kf][3] = *(const unsigned*)&qh[(size_t)(rlo + 8) * HD + kb + 8];
        }

        float O[4][4] = {};
        float l_lo = 0.f, l_hi = 0.f;

        for (int kc = 0; kc < 8; kc++) {
            float S[8][4] = {};
#pragma unroll
            for (int nt2 = 0; nt2 < 4; nt2++) {
                const int rowb = kc * 64 + nt2 * 16 + ((lane >> 4) << 3) + (lane & 7);
                const int colb2 = ((lane >> 3) & 1) * 16;   // bytes
#pragma unroll
                for (int kf = 0; kf < 2; kf++) {
                    const unsigned off = kswz(rowb, kf * 32 + colb2);
                    unsigned kh0, kh1, kh2, kh3;
                    ldsm4(kh0, kh1, kh2, kh3, smem_u32((char*)Khs + off));
                    mma16816(S[nt2 * 2],     qhf[kf][0], qhf[kf][1], qhf[kf][2], qhf[kf][3], kh0, kh1);
                    mma16816(S[nt2 * 2 + 1], qhf[kf][0], qhf[kf][1], qhf[kf][2], qhf[kf][3], kh2, kh3);
                }
            }

            // ---- fixed-max softmax numerator ----
#pragma unroll
            for (int nt = 0; nt < 8; nt++) {
                S[nt][0] = ex2(S[nt][0] - bias2);
                S[nt][1] = ex2(S[nt][1] - bias2);
                S[nt][2] = ex2(S[nt][2] - bias2);
                S[nt][3] = ex2(S[nt][3] - bias2);
                l_lo += S[nt][0] + S[nt][1];
                l_hi += S[nt][2] + S[nt][3];
            }

            // ---- PV ----
#pragma unroll
            for (int ks = 0; ks < 4; ks++) {
                const unsigned p0 = pack_h2(S[2 * ks][0], S[2 * ks][1]);
                const unsigned p1 = pack_h2(S[2 * ks][2], S[2 * ks][3]);
                const unsigned p2 = pack_h2(S[2 * ks + 1][0], S[2 * ks + 1][1]);
                const unsigned p3 = pack_h2(S[2 * ks + 1][2], S[2 * ks + 1][3]);
#pragma unroll
                for (int dt2 = 0; dt2 < 2; dt2++) {
                    const int rowd = dt2 * 16 + ((lane >> 4) << 3) + (lane & 7);
                    const int colk = kc * 64 + ks * 16 + ((lane >> 3) & 1) * 8;
                    unsigned v0, v1, v2, v3;
                    ldsm4(v0, v1, v2, v3, smem_u32(&Vts[rowd * 520 + colk]));
                    mma16816(O[dt2 * 2],     p0, p1, p2, p3, v0, v1);
                    mma16816(O[dt2 * 2 + 1], p0, p1, p2, p3, v2, v3);
                }
            }
        }

        // ---- final l reduction + write ----
        l_lo += __shfl_xor_sync(0xffffffffu, l_lo, 1);
        l_lo += __shfl_xor_sync(0xffffffffu, l_lo, 2);
        l_hi += __shfl_xor_sync(0xffffffffu, l_hi, 1);
        l_hi += __shfl_xor_sync(0xffffffffu, l_hi, 2);
        const float il_lo = 1.0f / l_lo, il_hi = 1.0f / l_hi;
#pragma unroll
        for (int dt = 0; dt < 4; dt++) {
            __half2 o_lo = __floats2half2_rn(O[dt][0] * il_lo, O[dt][1] * il_lo);
            __half2 o_hi = __floats2half2_rn(O[dt][2] * il_hi, O[dt][3] * il_hi);
            const size_t base = ((size_t)b * SEQ + rlo) * C_DIM + h * HD + dt * 8 + (lane & 3) * 2;
            *(__half2*)&g_attno[base] = o_lo;
            *(__half2*)&g_attno[base + (size_t)8 * C_DIM] = o_hi;
        }
    }
}

// ============================================================
// Launch
// ============================================================
extern "C" void kernel_launch(void* const* d_in, const int* in_sizes, int n_in,
                              void* d_out, int out_size)
{
    (void)in_sizes; (void)n_in; (void)out_size;
    const float* x1     = (const float*)d_in[0];
    const float* x2     = (const float*)d_in[1];
    const float* q_w    = (const float*)d_in[2];
    const float* q_b    = (const float*)d_in[3];
    const float* kv_w   = (const float*)d_in[4];
    const float* v_b    = (const float*)d_in[5];
    const float* ls     = (const float*)d_in[6];
    const float* proj_w = (const float*)d_in[7];
    const float* proj_b = (const float*)d_in[8];
    float* out = (float*)d_out;

    __half *x1h, *x2h, *wqh, *wql, *wkvh, *wkvl, *wph, *wpl, *attno;
    cudaGetSymbolAddress((void**)&x1h,  g_x1h);
    cudaGetSymbolAddress((void**)&x2h,  g_x2h);
    cudaGetSymbolAddress((void**)&wqh,  g_wqh);  cudaGetSymbolAddress((void**)&wql,  g_wql);
    cudaGetSymbolAddress((void**)&wkvh, g_wkvh); cudaGetSymbolAddress((void**)&wkvl, g_wkvl);
    cudaGetSymbolAddress((void**)&wph,  g_wph);  cudaGetSymbolAddress((void**)&wpl,  g_wpl);
    cudaGetSymbolAddress((void**)&attno, g_attno);

    // 6144 blocks per tensor (1,572,864 items / 256 threads)
    tohalf2_kernel<<<12288, 256>>>(x1, x2);
    split3_kernel<<<72, 256>>>(q_w, kv_w, proj_w);

    // q projection + fused normalize/scale(log2e) -> g_qh
    gemm_kernel<C_DIM, 0><<<dim3(C_DIM / 64, MROWS / 128), 256>>>(x1h, wqh, wql, q_b, ls, nullptr);
    // kv projection + fused k-normalize -> g_kh; v -> g_vt
    gemm_kernel<2 * C_DIM, 1><<<dim3(2 * C_DIM / 64, MROWS / 128), 256>>>(x2h, wkvh, wkvl, v_b, nullptr, nullptr);

    const int smem_bytes = (512 * 32 + 32 * 520) * (int)sizeof(__half); // 66048
    cudaFuncSetAttribute(attn_kernel, cudaFuncAttributeMaxDynamicSharedMemorySize, smem_bytes);
    attn_kernel<<<BH, 256, smem_bytes>>>(ls);

    // output projection
    gemm_kernel<C_DIM, 2><<<dim3(C_DIM / 64, MROWS / 128), 256>>>(attno, wph, wpl, proj_b, nullptr, out);
}